// round 11
// baseline (speedup 1.0000x reference)
#include <cuda_runtime.h>
#include <cuda_bf16.h>
#include <math.h>
#include <stdint.h>

#define DIMN   1024
#define SEQL   1024
#define BATCHN 4
#define NTOK   (BATCHN*SEQL)     /* 4096 */
#define NBLK   (BATCHN*128)      /* 512 tokens of vec */
#define EPSV   1e-6f

typedef __nv_bfloat16 bf16;

/* ---------------- scratch (device globals: no allocation allowed) -------- */
__device__ float g_mod_a[NBLK*3*DIMN];
__device__ float g_mod_f[NBLK*3*DIMN];
__device__ float g_h[NTOK*DIMN];
__device__ float g_g1[NTOK*DIMN];
__device__ float g_g3[NTOK*DIMN];
/* bf16 hi/lo activation buffers */
__device__ bf16 g_svh[NBLK*DIMN],  g_svl[NBLK*DIMN];
__device__ bf16 g_xnh[NTOK*DIMN],  g_xnl[NTOK*DIMN];
__device__ bf16 g_hnh[NTOK*DIMN],  g_hnl[NTOK*DIMN];
__device__ bf16 g_ath[NTOK*DIMN],  g_atl[NTOK*DIMN];
__device__ bf16 g_g1h[NTOK*DIMN],  g_g1l[NTOK*DIMN];
/* rope'd Q/K and V as packed bf16x2 words, hi and lo */
__device__ uint32_t g_qh[NTOK*512], g_ql[NTOK*512];
__device__ uint32_t g_kh[NTOK*128], g_kl[NTOK*128];
__device__ uint32_t g_vh[NTOK*128], g_vl[NTOK*128];
/* weight hi/lo pool */
#define OWQ  0
#define OWK  1048576
#define OWV  1310720
#define OWO  1572864
#define OW1  2621440
#define OW3  3670016
#define OW2  4718592
#define OMA  5767168
#define OMF  8912896
#define WPOOL 12058624
__device__ bf16 g_wh[WPOOL], g_wl[WPOOL];

/* ---------------- helpers ------------------------------------------------ */
__device__ __forceinline__ uint32_t pack_hi(float x, float y) {
    return __byte_perm(__float_as_uint(x), __float_as_uint(y), 0x7632);
}
__device__ __forceinline__ float hi_part(float x) {
    return __uint_as_float(__float_as_uint(x) & 0xFFFF0000u);
}
__device__ __forceinline__ uint32_t smem_u32(const void* p) {
    uint32_t a;
    asm("{ .reg .u64 t; cvta.to.shared.u64 t, %1; cvt.u32.u64 %0, t; }"
        : "=r"(a) : "l"(p));
    return a;
}
/* word index in a tile with 16-word rows, conflict-free XOR swizzle */
__device__ __forceinline__ int sww16(int r, int w) {
    return r*16 + (w ^ (((r >> 1) & 3) << 2));
}
/* word index, 32-word rows */
__device__ __forceinline__ int sww32(int r, int w) {
    return r*32 + (w ^ ((r & 7) << 2));
}
__device__ __forceinline__ void mma_bf16(float* c, const uint32_t* a,
                                         const uint32_t* b) {
    asm volatile(
        "mma.sync.aligned.m16n8k16.row.col.f32.bf16.bf16.f32 "
        "{%0,%1,%2,%3}, {%4,%5,%6,%7}, {%8,%9}, {%0,%1,%2,%3};"
        : "+f"(c[0]), "+f"(c[1]), "+f"(c[2]), "+f"(c[3])
        : "r"(a[0]), "r"(a[1]), "r"(a[2]), "r"(a[3]), "r"(b[0]), "r"(b[1]));
}
#define LDSM4(r0,r1,r2,r3, a) \
    asm volatile("ldmatrix.sync.aligned.m8n8.x4.shared.b16 {%0,%1,%2,%3}, [%4];" \
        : "=r"(r0),"=r"(r1),"=r"(r2),"=r"(r3) : "r"(a))
#define LDSM4T(r0,r1,r2,r3, a) \
    asm volatile("ldmatrix.sync.aligned.m8n8.x4.trans.shared.b16 {%0,%1,%2,%3}, [%4];" \
        : "=r"(r0),"=r"(r1),"=r"(r2),"=r"(r3) : "r"(a))
#define CPA16(dst, src) \
    asm volatile("cp.async.cg.shared.global [%0], [%1], 16;" \
        :: "r"(dst), "l"(src) : "memory")
#define CPCOMMIT() asm volatile("cp.async.commit_group;" ::: "memory")
#define CPWAIT0()  asm volatile("cp.async.wait_group 0;" ::: "memory")
/* fast exp on FMA pipe */
__device__ __forceinline__ float fexp(float x) {
    float t = fmaxf(x * 1.44269504f, -126.f);
    float fi = floorf(t);
    float f = t - fi;
    float p = fmaf(f, 0.00133336f, 0.00961812f);
    p = fmaf(f, p, 0.05550411f);
    p = fmaf(f, p, 0.24022651f);
    p = fmaf(f, p, 0.69314718f);
    p = fmaf(f, p, 1.0f);
    return __int_as_float(((int)fi + 127) << 23) * p;
}

/* ------------- split-bf16 GEMM via cp.async + ldmatrix -------------------- */
#define GSMEM 98304

#define GISSUE(s_) do {                                                        \
    int kof = (s_)*32;                                                         \
    _Pragma("unroll")                                                          \
    for (int i = 0; i < 8; i++) {                                              \
        int id = tid + i*256;                                                  \
        int part = id >> 9, loc = id & 511;                                    \
        int row = loc >> 2, ch = loc & 3;                                      \
        const bf16* sp = (part==0) ? srcAh : (part==1) ? srcAl                 \
                       : (part==2) ? srcBh : srcBl;                            \
        const bf16* src = sp + (size_t)row*K + kof + ch*8;                     \
        uint32_t dst = sb + (uint32_t)((((s_)%3)*8192 + part*2048              \
                       + sww16(row, ch*4)) * 4);                               \
        CPA16(dst, src);                                                       \
    }                                                                          \
} while (0)

/* MODE 0: single B/C. MODE 1: qkv (3 Bs). MODE 2: dual B/C split by bx.     */
/* EPI 0: C=acc; EPI 1: +bias; EPI 2: resid+mod*acc; EPI 3: rope->q/k/v bufs */
template<int EPI, int MODE>
__global__ __launch_bounds__(256, 2) void gemm_bf(
    const bf16* __restrict__ Ah, const bf16* __restrict__ Al,
    const bf16* __restrict__ Bh0, const bf16* __restrict__ Bl0,
    const bf16* __restrict__ Bh1, const bf16* __restrict__ Bl1,
    const bf16* __restrict__ Bh2, const bf16* __restrict__ Bl2,
    float* __restrict__ C0, float* __restrict__ C1, int ldc,
    int K, int split,
    const float* __restrict__ bias0, const float* __restrict__ bias1,
    const float* __restrict__ resid, int ldr,
    const float* __restrict__ mod, int goff) {
    extern __shared__ uint32_t swm[];
    int tid = threadIdx.x, lane = tid & 31, wid = tid >> 5;
    int wm = wid >> 1, wn = wid & 1;
    int g4 = lane >> 2, t4 = lane & 3;
    int lr = lane & 7, sel = lane >> 3;
    int aro = (sel & 1)*8 + lr, awo = (sel >> 1)*4;
    int bro = (sel >> 1)*8 + lr, bwo = (sel & 1)*4;
    int bx = blockIdx.x, m0 = blockIdx.y*128;
    int n0glob = bx*128;

    const bf16 *Bh, *Bl; float* Cg = nullptr; const float* bias = nullptr;
    int n0loc, row0;
    if (MODE == 0) {
        Bh = Bh0; Bl = Bl0; row0 = n0glob; Cg = C0 + n0glob;
        bias = bias0; n0loc = n0glob;
    } else if (MODE == 1) {
        if (n0glob < 1024)      { Bh = Bh0; Bl = Bl0; row0 = n0glob; }
        else if (n0glob < 1280) { Bh = Bh1; Bl = Bl1; row0 = n0glob-1024; }
        else                    { Bh = Bh2; Bl = Bl2; row0 = n0glob-1280; }
        n0loc = n0glob;
    } else {
        int sel2 = bx >= split; int nb = bx - (sel2 ? split : 0);
        n0loc = nb*128; row0 = n0loc;
        Bh = sel2 ? Bh1 : Bh0;  Bl = sel2 ? Bl1 : Bl0;
        Cg = (sel2 ? C1 : C0) + n0loc;
        bias = sel2 ? bias1 : bias0;
    }
    const bf16* srcAh = Ah + (size_t)m0*K;
    const bf16* srcAl = Al + (size_t)m0*K;
    const bf16* srcBh = Bh + (size_t)row0*K;
    const bf16* srcBl = Bl + (size_t)row0*K;
    uint32_t sb = smem_u32(swm);

    int nk = K >> 5;
    GISSUE(0);
    CPCOMMIT();
    GISSUE(1);
    CPCOMMIT();

    float acc[2][8][4];
    #pragma unroll
    for (int mt=0;mt<2;mt++)
        #pragma unroll
        for (int nt=0;nt<8;nt++)
            #pragma unroll
            for (int e=0;e<4;e++) acc[mt][nt][e]=0.f;

    for (int s = 0; s < nk; s++) {
        asm volatile("cp.async.wait_group 1;" ::: "memory");
        __syncthreads();
        uint32_t stoff = (uint32_t)((s%3)*8192*4);
        #pragma unroll
        for (int half = 0; half < 2; half++) {
            int w0 = half*8;
            uint32_t ah[2][4], al[2][4], bh[8][2], bl[8][2];
            #pragma unroll
            for (int mt = 0; mt < 2; mt++) {
                int r = wm*32 + mt*16 + aro;
                uint32_t ad = sb + stoff + (uint32_t)sww16(r, w0+awo)*4;
                LDSM4(ah[mt][0],ah[mt][1],ah[mt][2],ah[mt][3], ad);
                LDSM4(al[mt][0],al[mt][1],al[mt][2],al[mt][3], ad + 8192);
            }
            #pragma unroll
            for (int ntp = 0; ntp < 8; ntp += 2) {
                int r = wn*64 + ntp*8 + bro;
                uint32_t ad = sb + stoff + 16384 + (uint32_t)sww16(r, w0+bwo)*4;
                LDSM4(bh[ntp][0],bh[ntp][1],bh[ntp+1][0],bh[ntp+1][1], ad);
                LDSM4(bl[ntp][0],bl[ntp][1],bl[ntp+1][0],bl[ntp+1][1], ad + 8192);
            }
            #pragma unroll
            for (int nt = 0; nt < 8; nt++)
                #pragma unroll
                for (int mt = 0; mt < 2; mt++) {
                    mma_bf16(acc[mt][nt], ah[mt], bh[nt]);
                    mma_bf16(acc[mt][nt], ah[mt], bl[nt]);
                    mma_bf16(acc[mt][nt], al[mt], bh[nt]);
                }
        }
        if (s + 2 < nk) { GISSUE(s+2); }
        CPCOMMIT();
    }

    #pragma unroll
    for (int mt = 0; mt < 2; mt++) {
        int rb0 = m0 + wm*32 + mt*16 + g4;
        #pragma unroll
        for (int h = 0; h < 2; h++) {
            int m = rb0 + h*8;
            #pragma unroll
            for (int nt = 0; nt < 8; nt++) {
                int nl = wn*64 + nt*8 + 2*t4;
                float2 a2 = make_float2(acc[mt][nt][2*h], acc[mt][nt][2*h+1]);
                if (EPI == 3) {
                    int ng = n0loc + nl;
                    if (ng < 1280) {
                        int t = m & (SEQL-1); int dp = (ng & 63) >> 1;
                        float c = bias0[t*32+dp], sn = bias1[t*32+dp];
                        float r0 = a2.x*c - a2.y*sn, r1 = a2.x*sn + a2.y*c;
                        a2.x = r0; a2.y = r1;
                    }
                    uint32_t hw = pack_hi(a2.x, a2.y);
                    uint32_t lw = pack_hi(a2.x-hi_part(a2.x), a2.y-hi_part(a2.y));
                    if (ng < 1024) {
                        g_qh[(size_t)m*512 + (ng>>1)] = hw;
                        g_ql[(size_t)m*512 + (ng>>1)] = lw;
                    } else if (ng < 1280) {
                        int c = (ng-1024)>>1;
                        g_kh[(size_t)m*128 + c] = hw;
                        g_kl[(size_t)m*128 + c] = lw;
                    } else {
                        int c = (ng-1280)>>1;
                        g_vh[(size_t)m*128 + c] = hw;
                        g_vl[(size_t)m*128 + c] = lw;
                    }
                } else {
                    float2 o;
                    if (EPI == 0) {
                        o = a2;
                    } else if (EPI == 1) {
                        const float2 bv = *(const float2*)(bias + n0loc + nl);
                        o.x = a2.x + bv.x; o.y = a2.y + bv.y;
                    } else {
                        int ng = n0loc + nl;
                        const float2 gv = *(const float2*)(mod + (size_t)(m>>3)*(3*DIMN) + goff + ng);
                        const float2 rv = *(const float2*)(resid + (size_t)m*ldr + ng);
                        o.x = rv.x + gv.x*a2.x;
                        o.y = rv.y + gv.y*a2.y;
                    }
                    *(float2*)(Cg + (size_t)m*ldc + nl) = o;
                }
            }
        }
    }
}

/* ---------------- fused weight convert ------------------------------------ */
__global__ __launch_bounds__(256) void conv_all(
    const float* __restrict__ wq, const float* __restrict__ wk,
    const float* __restrict__ wv, const float* __restrict__ wo,
    const float* __restrict__ w1, const float* __restrict__ w3,
    const float* __restrict__ w2, const float* __restrict__ maw,
    const float* __restrict__ mfw,
    bf16* __restrict__ wh, bf16* __restrict__ wl) {
    int bb = blockIdx.x;
    const float* src; int loc, dof;
    if      (bb < 1024)  { src = wq;  loc = bb;       dof = OWQ; }
    else if (bb < 1280)  { src = wk;  loc = bb-1024;  dof = OWK; }
    else if (bb < 1536)  { src = wv;  loc = bb-1280;  dof = OWV; }
    else if (bb < 2560)  { src = wo;  loc = bb-1536;  dof = OWO; }
    else if (bb < 3584)  { src = w1;  loc = bb-2560;  dof = OW1; }
    else if (bb < 4608)  { src = w3;  loc = bb-3584;  dof = OW3; }
    else if (bb < 5632)  { src = w2;  loc = bb-4608;  dof = OW2; }
    else if (bb < 8704)  { src = maw; loc = bb-5632;  dof = OMA; }
    else                 { src = mfw; loc = bb-8704;  dof = OMF; }
    int i = loc*256 + threadIdx.x;
    float4 v = ((const float4*)src)[i];
    ((uint2*)(wh + dof))[i] = make_uint2(pack_hi(v.x,v.y), pack_hi(v.z,v.w));
    float lx=v.x-hi_part(v.x), ly=v.y-hi_part(v.y);
    float lz=v.z-hi_part(v.z), lw=v.w-hi_part(v.w);
    ((uint2*)(wl + dof))[i] = make_uint2(pack_hi(lx,ly), pack_hi(lz,lw));
}

/* ---------------- elementwise kernels ------------------------------------ */
__global__ __launch_bounds__(256) void silu_kernel(
    const float* __restrict__ in, bf16* __restrict__ hi, bf16* __restrict__ lo) {
    int i = blockIdx.x * 256 + threadIdx.x;
    float4 v = ((const float4*)in)[i];
    float4 o;
    o.x = v.x / (1.f + __expf(-v.x));
    o.y = v.y / (1.f + __expf(-v.y));
    o.z = v.z / (1.f + __expf(-v.z));
    o.w = v.w / (1.f + __expf(-v.w));
    ((uint2*)hi)[i] = make_uint2(pack_hi(o.x,o.y), pack_hi(o.z,o.w));
    float lx=o.x-hi_part(o.x), ly=o.y-hi_part(o.y);
    float lz=o.z-hi_part(o.z), lw=o.w-hi_part(o.w);
    ((uint2*)lo)[i] = make_uint2(pack_hi(lx,ly), pack_hi(lz,lw));
}

__global__ __launch_bounds__(256) void swiglu_kernel(
    const float* __restrict__ g1, const float* __restrict__ g3,
    bf16* __restrict__ hi, bf16* __restrict__ lo) {
    int i = blockIdx.x * 256 + threadIdx.x;
    float4 a = ((const float4*)g1)[i];
    float4 b = ((const float4*)g3)[i];
    float4 o;
    o.x = (a.x / (1.f + __expf(-a.x))) * b.x;
    o.y = (a.y / (1.f + __expf(-a.y))) * b.y;
    o.z = (a.z / (1.f + __expf(-a.z))) * b.z;
    o.w = (a.w / (1.f + __expf(-a.w))) * b.w;
    ((uint2*)hi)[i] = make_uint2(pack_hi(o.x,o.y), pack_hi(o.z,o.w));
    float lx=o.x-hi_part(o.x), ly=o.y-hi_part(o.y);
    float lz=o.z-hi_part(o.z), lw=o.w-hi_part(o.w);
    ((uint2*)lo)[i] = make_uint2(pack_hi(lx,ly), pack_hi(lz,lw));
}

__global__ __launch_bounds__(256) void rmsnorm_mod_kernel(
    const float* __restrict__ X, const float* __restrict__ w,
    const float* __restrict__ mod, bf16* __restrict__ oh, bf16* __restrict__ ol) {
    int m = blockIdx.x;
    int tid = threadIdx.x;
    float4 v = ((const float4*)(X + (size_t)m*DIMN))[tid];
    float ss = v.x*v.x + v.y*v.y + v.z*v.z + v.w*v.w;
    #pragma unroll
    for (int o = 16; o; o >>= 1) ss += __shfl_xor_sync(0xffffffffu, ss, o);
    __shared__ float red[8];
    if ((tid & 31) == 0) red[tid >> 5] = ss;
    __syncthreads();
    float tot = red[0]+red[1]+red[2]+red[3]+red[4]+red[5]+red[6]+red[7];
    float rms = rsqrtf(tot * (1.f/DIMN) + EPSV);
    const float* mrow = mod + (size_t)(m >> 3) * (3*DIMN);
    float4 sh = *(const float4*)(mrow + tid*4);
    float4 sc = *(const float4*)(mrow + DIMN + tid*4);
    float4 wv = ((const float4*)w)[tid];
    float4 o;
    o.x = v.x*rms*wv.x*(1.f+sc.x) + sh.x;
    o.y = v.y*rms*wv.y*(1.f+sc.y) + sh.y;
    o.z = v.z*rms*wv.z*(1.f+sc.z) + sh.z;
    o.w = v.w*rms*wv.w*(1.f+sc.w) + sh.w;
    ((uint2*)(oh + (size_t)m*DIMN))[tid] = make_uint2(pack_hi(o.x,o.y), pack_hi(o.z,o.w));
    float lx=o.x-hi_part(o.x), ly=o.y-hi_part(o.y);
    float lz=o.z-hi_part(o.z), lw=o.w-hi_part(o.w);
    ((uint2*)(ol + (size_t)m*DIMN))[tid] = make_uint2(pack_hi(lx,ly), pack_hi(lz,lw));
}

/* ---------------- mma block-causal flash attention ------------------------ */
/* CTA: 128 q-rows, 1 head, 1 batch. 8 warps x 16 rows. cp.async + ldmatrix. */
/* smem words: Qh[0) Ql[4096) Kh[8192) Kl[10240) Vh[12288) Vl[14336)         */
#define ATT_SMEM 65536

__global__ __launch_bounds__(256, 2) void attn_kernel(
    bf16* __restrict__ outh, bf16* __restrict__ outl) {
    extern __shared__ uint32_t sm[];
    int qt2 = blockIdx.x, h = blockIdx.y, b = blockIdx.z;
    int tid = threadIdx.x, lane = tid & 31, wid = tid >> 5;
    int g4 = lane >> 2, t4 = lane & 3;
    int lr = lane & 7, sel = lane >> 3;
    int aro = (sel & 1)*8 + lr, awo = (sel >> 1)*4;
    int bro = (sel >> 1)*8 + lr, bwo = (sel & 1)*4;
    int vro = (sel & 1)*8 + lr, vwo = (sel >> 1)*4;
    uint32_t sb = smem_u32(sm);

    /* async-load Q (128 rows x 32 words) hi+lo */
    {
        const uint32_t* qs  = g_qh + (size_t)(b*SEQL + qt2*128)*512 + h*32;
        const uint32_t* qsl = g_ql + (size_t)(b*SEQL + qt2*128)*512 + h*32;
        #pragma unroll
        for (int i = 0; i < 4; i++) {
            int id = tid + i*256;
            int r = id >> 3, ch = (id & 7)*4;
            uint32_t d = (uint32_t)sww32(r, ch)*4;
            CPA16(sb + d,         qs  + (size_t)r*512 + ch);
            CPA16(sb + 16384 + d, qsl + (size_t)r*512 + ch);
        }
    }

    int kmax = 2*qt2 + (wid >> 2);
    int rb01 = (wid & 3)*2, rb23 = rb01 + 1;
    int base_r = wid*16;
    float s[8][4], o[8][4];
    float m0 = -1e30f, m1 = -1e30f, l0 = 0.f, l1 = 0.f;
    #pragma unroll
    for (int nt=0;nt<8;nt++)
        #pragma unroll
        for (int e=0;e<4;e++) o[nt][e]=0.f;

    int ktend = 2*qt2 + 1;
    for (int kt = 0; kt <= ktend; kt++) {
        __syncthreads();
        /* async-load K and V tiles (64 x 32 words) hi+lo */
        {
            size_t rowb = (size_t)(b*SEQL + kt*64)*128 + (h>>2)*32;
            #pragma unroll
            for (int i = 0; i < 2; i++) {
                int id = tid + i*256;
                int r = id >> 3, ch = (id & 7)*4;
                uint32_t d = (uint32_t)sww32(r, ch)*4;
                size_t src = rowb + (size_t)r*128 + ch;
                CPA16(sb + 32768 + d, g_kh + src);
                CPA16(sb + 40960 + d, g_kl + src);
                CPA16(sb + 49152 + d, g_vh + src);
                CPA16(sb + 57344 + d, g_vl + src);
            }
        }
        CPCOMMIT(); CPWAIT0();
        __syncthreads();
        if (kt > kmax) continue;

        /* S = Q @ K^T (split bf16, ldmatrix) */
        #pragma unroll
        for (int nt=0;nt<8;nt++)
            #pragma unroll
            for (int e=0;e<4;e++) s[nt][e]=0.f;
        #pragma unroll
        for (int ks = 0; ks < 4; ks++) {
            int w0 = ks*8;
            uint32_t ah[4], al[4], bh[8][2], bl[8][2];
            {
                int r = base_r + aro;
                uint32_t ad = sb + (uint32_t)sww32(r, w0+awo)*4;
                LDSM4(ah[0],ah[1],ah[2],ah[3], ad);
                LDSM4(al[0],al[1],al[2],al[3], ad + 16384);
            }
            #pragma unroll
            for (int ntp = 0; ntp < 8; ntp += 2) {
                int r = ntp*8 + bro;
                uint32_t ad = sb + 32768 + (uint32_t)sww32(r, w0+bwo)*4;
                LDSM4(bh[ntp][0],bh[ntp][1],bh[ntp+1][0],bh[ntp+1][1], ad);
                LDSM4(bl[ntp][0],bl[ntp][1],bl[ntp+1][0],bl[ntp+1][1], ad + 8192);
            }
            #pragma unroll
            for (int nt = 0; nt < 8; nt++) {
                mma_bf16(s[nt], ah, bh[nt]);
                mma_bf16(s[nt], ah, bl[nt]);
                mma_bf16(s[nt], al, bh[nt]);
            }
        }
        #pragma unroll
        for (int nt=0;nt<8;nt++)
            #pragma unroll
            for (int e=0;e<4;e++) s[nt][e] *= 0.125f;
        if (kt == kmax) {
            #pragma unroll
            for (int nt=0;nt<8;nt++) {
                if (nt > rb01) { s[nt][0] = -1e30f; s[nt][1] = -1e30f; }
                if (nt > rb23) { s[nt][2] = -1e30f; s[nt][3] = -1e30f; }
            }
        }
        /* online softmax */
        float mx0 = -1e30f, mx1 = -1e30f;
        #pragma unroll
        for (int nt=0;nt<8;nt++) {
            mx0 = fmaxf(mx0, fmaxf(s[nt][0], s[nt][1]));
            mx1 = fmaxf(mx1, fmaxf(s[nt][2], s[nt][3]));
        }
        mx0 = fmaxf(mx0, __shfl_xor_sync(0xffffffffu, mx0, 1));
        mx0 = fmaxf(mx0, __shfl_xor_sync(0xffffffffu, mx0, 2));
        mx1 = fmaxf(mx1, __shfl_xor_sync(0xffffffffu, mx1, 1));
        mx1 = fmaxf(mx1, __shfl_xor_sync(0xffffffffu, mx1, 2));
        float nm0 = fmaxf(m0, mx0), nm1 = fmaxf(m1, mx1);
        float al0 = fexp(m0 - nm0), al1 = fexp(m1 - nm1);
        m0 = nm0; m1 = nm1;
        float sum0 = 0.f, sum1 = 0.f;
        #pragma unroll
        for (int nt=0;nt<8;nt++) {
            s[nt][0] = fexp(s[nt][0] - m0);
            s[nt][1] = fexp(s[nt][1] - m0);
            s[nt][2] = fexp(s[nt][2] - m1);
            s[nt][3] = fexp(s[nt][3] - m1);
            sum0 += s[nt][0] + s[nt][1];
            sum1 += s[nt][2] + s[nt][3];
        }
        sum0 += __shfl_xor_sync(0xffffffffu, sum0, 1);
        sum0 += __shfl_xor_sync(0xffffffffu, sum0, 2);
        sum1 += __shfl_xor_sync(0xffffffffu, sum1, 1);
        sum1 += __shfl_xor_sync(0xffffffffu, sum1, 2);
        l0 = l0*al0 + sum0;
        l1 = l1*al1 + sum1;
        #pragma unroll
        for (int nt=0;nt<8;nt++) {
            o[nt][0] *= al0; o[nt][1] *= al0;
            o[nt][2] *= al1; o[nt][3] *= al1;
        }
        /* O += P @ V (V^T via ldmatrix.trans) */
        #pragma unroll
        for (int ks = 0; ks < 4; ks++) {
            uint32_t ph[4], pl[4], bh[8][2], bl[8][2];
            ph[0] = pack_hi(s[2*ks][0],   s[2*ks][1]);
            ph[1] = pack_hi(s[2*ks][2],   s[2*ks][3]);
            ph[2] = pack_hi(s[2*ks+1][0], s[2*ks+1][1]);
            ph[3] = pack_hi(s[2*ks+1][2], s[2*ks+1][3]);
            pl[0] = pack_hi(s[2*ks][0]-hi_part(s[2*ks][0]),
                            s[2*ks][1]-hi_part(s[2*ks][1]));
            pl[1] = pack_hi(s[2*ks][2]-hi_part(s[2*ks][2]),
                            s[2*ks][3]-hi_part(s[2*ks][3]));
            pl[2] = pack_hi(s[2*ks+1][0]-hi_part(s[2*ks+1][0]),
                            s[2*ks+1][1]-hi_part(s[2*ks+1][1]));
            pl[3] = pack_hi(s[2*ks+1][2]-hi_part(s[2*ks+1][2]),
                            s[2*ks+1][3]-hi_part(s[2*ks+1][3]));
            #pragma unroll
            for (int ntp = 0; ntp < 8; ntp += 2) {
                int rt = ks*16 + vro;
                uint32_t ad = sb + 49152 +
                    (uint32_t)sww32(rt, ntp*4 + vwo)*4;
                LDSM4T(bh[ntp][0],bh[ntp][1],bh[ntp+1][0],bh[ntp+1][1], ad);
                LDSM4T(bl[ntp][0],bl[ntp][1],bl[ntp+1][0],bl[ntp+1][1], ad + 8192);
            }
            #pragma unroll
            for (int nt = 0; nt < 8; nt++) {
                mma_bf16(o[nt], ph, bh[nt]);
                mma_bf16(o[nt], ph, bl[nt]);
                mma_bf16(o[nt], pl, bh[nt]);
            }
        }
    }

    /* normalize and write bf16 hi/lo */
    float i0 = 1.f / l0, i1 = 1.f / l1;
    int tok0 = b*SEQL + qt2*128 + base_r + g4;
    #pragma unroll
    for (int nt = 0; nt < 8; nt++) {
        int col = h*64 + nt*8 + 2*t4;
        float x0 = o[nt][0]*i0, x1 = o[nt][1]*i0;
        float x2 = o[nt][2]*i1, x3 = o[nt][3]*i1;
        ((uint32_t*)outh)[((size_t)tok0*DIMN + col) >> 1] = pack_hi(x0, x1);
        ((uint32_t*)outl)[((size_t)tok0*DIMN + col) >> 1] =
            pack_hi(x0-hi_part(x0), x1-hi_part(x1));
        ((uint32_t*)outh)[((size_t)(tok0+8)*DIMN + col) >> 1] = pack_hi(x2, x3);
        ((uint32_t*)outl)[((size_t)(tok0+8)*DIMN + col) >> 1] =
            pack_hi(x2-hi_part(x2), x3-hi_part(x3));
    }
}

/* ---------------- host launcher ------------------------------------------ */
extern "C" void kernel_launch(void* const* d_in, const int* in_sizes, int n_in,
                              void* d_out, int out_size) {
    const float *x,*vec,*wq,*wk,*wv,*wo,*w1,*w2,*w3,*maw,*mab,*mfw,*mfb,*n1,*n2,*fc,*fs;
    if (in_sizes[2] == 32768) {                   /* reference-argument order */
        x  =(const float*)d_in[0];  vec=(const float*)d_in[1];
        fc =(const float*)d_in[2];  fs =(const float*)d_in[3];
        wq =(const float*)d_in[4];  wk =(const float*)d_in[5];
        wv =(const float*)d_in[6];  wo =(const float*)d_in[7];
        w1 =(const float*)d_in[8];  w2 =(const float*)d_in[9];
        w3 =(const float*)d_in[10];
        maw=(const float*)d_in[11]; mab=(const float*)d_in[12];
        mfw=(const float*)d_in[13]; mfb=(const float*)d_in[14];
        n1 =(const float*)d_in[15]; n2 =(const float*)d_in[16];
    } else {                                      /* setup_inputs dict order */
        x  =(const float*)d_in[0];  vec=(const float*)d_in[1];
        wq =(const float*)d_in[2];  wk =(const float*)d_in[3];
        wv =(const float*)d_in[4];  wo =(const float*)d_in[5];
        w1 =(const float*)d_in[6];  w2 =(const float*)d_in[7];
        w3 =(const float*)d_in[8];
        maw=(const float*)d_in[9];  mab=(const float*)d_in[10];
        mfw=(const float*)d_in[11]; mfb=(const float*)d_in[12];
        n1 =(const float*)d_in[13]; n2 =(const float*)d_in[14];
        fc =(const float*)d_in[15]; fs =(const float*)d_in[16];
    }
    float* out = (float*)d_out;

    float *p_ma,*p_mf,*p_h,*p_g1,*p_g3;
    bf16 *p_svh,*p_svl,*p_xnh,*p_xnl,*p_hnh,*p_hnl,*p_ath,*p_atl,*p_g1h,*p_g1l,*p_wh,*p_wl;
    cudaGetSymbolAddress((void**)&p_ma,  g_mod_a);
    cudaGetSymbolAddress((void**)&p_mf,  g_mod_f);
    cudaGetSymbolAddress((void**)&p_h,   g_h);
    cudaGetSymbolAddress((void**)&p_g1,  g_g1);
    cudaGetSymbolAddress((void**)&p_g3,  g_g3);
    cudaGetSymbolAddress((void**)&p_svh, g_svh);
    cudaGetSymbolAddress((void**)&p_svl, g_svl);
    cudaGetSymbolAddress((void**)&p_xnh, g_xnh);
    cudaGetSymbolAddress((void**)&p_xnl, g_xnl);
    cudaGetSymbolAddress((void**)&p_hnh, g_hnh);
    cudaGetSymbolAddress((void**)&p_hnl, g_hnl);
    cudaGetSymbolAddress((void**)&p_ath, g_ath);
    cudaGetSymbolAddress((void**)&p_atl, g_atl);
    cudaGetSymbolAddress((void**)&p_g1h, g_g1h);
    cudaGetSymbolAddress((void**)&p_g1l, g_g1l);
    cudaGetSymbolAddress((void**)&p_wh,  g_wh);
    cudaGetSymbolAddress((void**)&p_wl,  g_wl);

    cudaFuncSetAttribute(attn_kernel,
                         cudaFuncAttributeMaxDynamicSharedMemorySize, ATT_SMEM);
    cudaFuncSetAttribute(gemm_bf<1,2>,
                         cudaFuncAttributeMaxDynamicSharedMemorySize, GSMEM);
    cudaFuncSetAttribute(gemm_bf<3,1>,
                         cudaFuncAttributeMaxDynamicSharedMemorySize, GSMEM);
    cudaFuncSetAttribute(gemm_bf<0,2>,
                         cudaFuncAttributeMaxDynamicSharedMemorySize, GSMEM);
    cudaFuncSetAttribute(gemm_bf<2,0>,
                         cudaFuncAttributeMaxDynamicSharedMemorySize, GSMEM);

    /* 0. all weight converts in one launch */
    conv_all<<<11776, 256>>>(wq, wk, wv, wo, w1, w3, w2, maw, mfw, p_wh, p_wl);

    /* 1. silu(vec) -> hi/lo */
    silu_kernel<<<512, 256>>>(vec, p_svh, p_svl);

    /* 2. both modulation GEMMs in one launch */
    gemm_bf<1,2><<<dim3(48,4), 256, GSMEM>>>(
        p_svh,p_svl, p_wh+OMA,p_wl+OMA, p_wh+OMF,p_wl+OMF, nullptr,nullptr,
        p_ma,p_mf,3*DIMN, DIMN, 24, mab,mfb, nullptr,0, nullptr,0);

    /* 3. xn -> hi/lo */
    rmsnorm_mod_kernel<<<NTOK, 256>>>(x, n1, p_ma, p_xnh, p_xnl);

    /* 4. QKV + fused RoPE -> q/k/v hi/lo buffers */
    gemm_bf<3,1><<<dim3(12,32), 256, GSMEM>>>(
        p_xnh,p_xnl, p_wh+OWQ,p_wl+OWQ, p_wh+OWK,p_wl+OWK, p_wh+OWV,p_wl+OWV,
        nullptr,nullptr,0, DIMN, 0, fc,fs, nullptr,0, nullptr,0);

    /* 5. mma block-causal attention -> hi/lo */
    attn_kernel<<<dim3(8,16,BATCHN), 256, ATT_SMEM>>>(p_ath, p_atl);

    /* 6. h = x + gate_a * (attn @ wo^T) */
    gemm_bf<2,0><<<dim3(8,32), 256, GSMEM>>>(
        p_ath,p_atl, p_wh+OWO,p_wl+OWO, nullptr,nullptr, nullptr,nullptr,
        p_h,nullptr,DIMN, DIMN, 0, nullptr,nullptr, x,DIMN, p_ma, 2*DIMN);

    /* 7. hn -> hi/lo */
    rmsnorm_mod_kernel<<<NTOK, 256>>>(p_h, n2, p_mf, p_hnh, p_hnl);

    /* 8. FFN up: w1 + w3 in one launch */
    gemm_bf<0,2><<<dim3(16,32), 256, GSMEM>>>(
        p_hnh,p_hnl, p_wh+OW1,p_wl+OW1, p_wh+OW3,p_wl+OW3, nullptr,nullptr,
        p_g1,p_g3,DIMN, DIMN, 8, nullptr,nullptr, nullptr,0, nullptr,0);

    /* 9. swiglu -> hi/lo */
    swiglu_kernel<<<4096, 256>>>(p_g1, p_g3, p_g1h, p_g1l);

    /* 10. out = h + gate_f * (swiglu @ w2^T) */
    gemm_bf<2,0><<<dim3(8,32), 256, GSMEM>>>(
        p_g1h,p_g1l, p_wh+OW2,p_wl+OW2, nullptr,nullptr, nullptr,nullptr,
        out,nullptr,DIMN, DIMN, 0, nullptr,nullptr, p_h,DIMN, p_mf, 2*DIMN);
}

// round 12
// speedup vs baseline: 1.4852x; 1.4852x over previous
#include <cuda_runtime.h>
#include <cuda_bf16.h>
#include <math.h>
#include <stdint.h>

#define DIMN   1024
#define SEQL   1024
#define BATCHN 4
#define NTOK   (BATCHN*SEQL)     /* 4096 */
#define NBLK   (BATCHN*128)      /* 512 tokens of vec */
#define EPSV   1e-6f

typedef __nv_bfloat16 bf16;

/* ---------------- scratch (device globals: no allocation allowed) -------- */
__device__ float g_mod_a[NBLK*3*DIMN];
__device__ float g_mod_f[NBLK*3*DIMN];
__device__ float g_h[NTOK*DIMN];
__device__ float g_g1[NTOK*DIMN];
__device__ float g_g3[NTOK*DIMN];
/* bf16 hi/lo activation buffers */
__device__ bf16 g_svh[NBLK*DIMN],  g_svl[NBLK*DIMN];
__device__ bf16 g_xnh[NTOK*DIMN],  g_xnl[NTOK*DIMN];
__device__ bf16 g_hnh[NTOK*DIMN],  g_hnl[NTOK*DIMN];
__device__ bf16 g_ath[NTOK*DIMN],  g_atl[NTOK*DIMN];
__device__ bf16 g_g1h[NTOK*DIMN],  g_g1l[NTOK*DIMN];
/* rope'd Q/K and V as packed bf16x2 words, hi and lo */
__device__ uint32_t g_qh[NTOK*512], g_ql[NTOK*512];
__device__ uint32_t g_kh[NTOK*128], g_kl[NTOK*128];
__device__ uint32_t g_vh[NTOK*128], g_vl[NTOK*128];
/* weight hi/lo pool */
#define OWQ  0
#define OWK  1048576
#define OWV  1310720
#define OWO  1572864
#define OW1  2621440
#define OW3  3670016
#define OW2  4718592
#define OMA  5767168
#define OMF  8912896
#define WPOOL 12058624
__device__ bf16 g_wh[WPOOL], g_wl[WPOOL];

/* ---------------- helpers ------------------------------------------------ */
__device__ __forceinline__ uint32_t pack_hi(float x, float y) {
    return __byte_perm(__float_as_uint(x), __float_as_uint(y), 0x7632);
}
__device__ __forceinline__ float hi_part(float x) {
    return __uint_as_float(__float_as_uint(x) & 0xFFFF0000u);
}
__device__ __forceinline__ uint32_t smem_u32(const void* p) {
    uint32_t a;
    asm("{ .reg .u64 t; cvta.to.shared.u64 t, %1; cvt.u32.u64 %0, t; }"
        : "=r"(a) : "l"(p));
    return a;
}
/* word index in a tile with 16-word rows, conflict-free XOR swizzle */
__device__ __forceinline__ int sww16(int r, int w) {
    return r*16 + (w ^ (((r >> 1) & 3) << 2));
}
/* word index, 32-word rows */
__device__ __forceinline__ int sww32(int r, int w) {
    return r*32 + (w ^ ((r & 7) << 2));
}
__device__ __forceinline__ void mma_bf16(float* c, const uint32_t* a,
                                         const uint32_t* b) {
    asm volatile(
        "mma.sync.aligned.m16n8k16.row.col.f32.bf16.bf16.f32 "
        "{%0,%1,%2,%3}, {%4,%5,%6,%7}, {%8,%9}, {%0,%1,%2,%3};"
        : "+f"(c[0]), "+f"(c[1]), "+f"(c[2]), "+f"(c[3])
        : "r"(a[0]), "r"(a[1]), "r"(a[2]), "r"(a[3]), "r"(b[0]), "r"(b[1]));
}
#define LDSM4(r0,r1,r2,r3, a) \
    asm volatile("ldmatrix.sync.aligned.m8n8.x4.shared.b16 {%0,%1,%2,%3}, [%4];" \
        : "=r"(r0),"=r"(r1),"=r"(r2),"=r"(r3) : "r"(a))
#define LDSM4T(r0,r1,r2,r3, a) \
    asm volatile("ldmatrix.sync.aligned.m8n8.x4.trans.shared.b16 {%0,%1,%2,%3}, [%4];" \
        : "=r"(r0),"=r"(r1),"=r"(r2),"=r"(r3) : "r"(a))
#define CPA16(dst, src) \
    asm volatile("cp.async.cg.shared.global [%0], [%1], 16;" \
        :: "r"(dst), "l"(src) : "memory")
#define CPCOMMIT() asm volatile("cp.async.commit_group;" ::: "memory")
#define CPWAIT0()  asm volatile("cp.async.wait_group 0;" ::: "memory")
/* fast exp on FMA pipe */
__device__ __forceinline__ float fexp(float x) {
    float t = fmaxf(x * 1.44269504f, -126.f);
    float fi = floorf(t);
    float f = t - fi;
    float p = fmaf(f, 0.00133336f, 0.00961812f);
    p = fmaf(f, p, 0.05550411f);
    p = fmaf(f, p, 0.24022651f);
    p = fmaf(f, p, 0.69314718f);
    p = fmaf(f, p, 1.0f);
    return __int_as_float(((int)fi + 127) << 23) * p;
}

/* ------------- split-bf16 GEMM via cp.async + ldmatrix -------------------- */
#define GSMEM 98304

#define GISSUE(s_) do {                                                        \
    int kof = (s_)*32;                                                         \
    _Pragma("unroll")                                                          \
    for (int i = 0; i < 8; i++) {                                              \
        int id = tid + i*256;                                                  \
        int part = id >> 9, loc = id & 511;                                    \
        int row = loc >> 2, ch = loc & 3;                                      \
        const bf16* sp = (part==0) ? srcAh : (part==1) ? srcAl                 \
                       : (part==2) ? srcBh : srcBl;                            \
        const bf16* src = sp + (size_t)row*K + kof + ch*8;                     \
        uint32_t dst = sb + (uint32_t)((((s_)%3)*8192 + part*2048              \
                       + sww16(row, ch*4)) * 4);                               \
        CPA16(dst, src);                                                       \
    }                                                                          \
} while (0)

/* MODE 0: single B/C. MODE 1: qkv (3 Bs). MODE 2: dual B/C split by bx.     */
/* EPI 0: C=acc; EPI 1: +bias; EPI 2: resid+mod*acc; EPI 3: rope->q/k/v bufs */
template<int EPI, int MODE>
__global__ __launch_bounds__(256, 2) void gemm_bf(
    const bf16* __restrict__ Ah, const bf16* __restrict__ Al,
    const bf16* __restrict__ Bh0, const bf16* __restrict__ Bl0,
    const bf16* __restrict__ Bh1, const bf16* __restrict__ Bl1,
    const bf16* __restrict__ Bh2, const bf16* __restrict__ Bl2,
    float* __restrict__ C0, float* __restrict__ C1, int ldc,
    int K, int split,
    const float* __restrict__ bias0, const float* __restrict__ bias1,
    const float* __restrict__ resid, int ldr,
    const float* __restrict__ mod, int goff) {
    extern __shared__ uint32_t swm[];
    int tid = threadIdx.x, lane = tid & 31, wid = tid >> 5;
    int wm = wid >> 1, wn = wid & 1;
    int g4 = lane >> 2, t4 = lane & 3;
    int lr = lane & 7, sel = lane >> 3;
    int aro = (sel & 1)*8 + lr, awo = (sel >> 1)*4;
    int bro = (sel >> 1)*8 + lr, bwo = (sel & 1)*4;
    int bx = blockIdx.x, m0 = blockIdx.y*128;
    int n0glob = bx*128;

    const bf16 *Bh, *Bl; float* Cg = nullptr; const float* bias = nullptr;
    int n0loc, row0;
    if (MODE == 0) {
        Bh = Bh0; Bl = Bl0; row0 = n0glob; Cg = C0 + n0glob;
        bias = bias0; n0loc = n0glob;
    } else if (MODE == 1) {
        if (n0glob < 1024)      { Bh = Bh0; Bl = Bl0; row0 = n0glob; }
        else if (n0glob < 1280) { Bh = Bh1; Bl = Bl1; row0 = n0glob-1024; }
        else                    { Bh = Bh2; Bl = Bl2; row0 = n0glob-1280; }
        n0loc = n0glob;
    } else {
        int sel2 = bx >= split; int nb = bx - (sel2 ? split : 0);
        n0loc = nb*128; row0 = n0loc;
        Bh = sel2 ? Bh1 : Bh0;  Bl = sel2 ? Bl1 : Bl0;
        Cg = (sel2 ? C1 : C0) + n0loc;
        bias = sel2 ? bias1 : bias0;
    }
    const bf16* srcAh = Ah + (size_t)m0*K;
    const bf16* srcAl = Al + (size_t)m0*K;
    const bf16* srcBh = Bh + (size_t)row0*K;
    const bf16* srcBl = Bl + (size_t)row0*K;
    uint32_t sb = smem_u32(swm);

    int nk = K >> 5;
    GISSUE(0);
    CPCOMMIT();
    GISSUE(1);
    CPCOMMIT();

    float acc[2][8][4];
    #pragma unroll
    for (int mt=0;mt<2;mt++)
        #pragma unroll
        for (int nt=0;nt<8;nt++)
            #pragma unroll
            for (int e=0;e<4;e++) acc[mt][nt][e]=0.f;

    for (int s = 0; s < nk; s++) {
        asm volatile("cp.async.wait_group 1;" ::: "memory");
        __syncthreads();
        uint32_t stoff = (uint32_t)((s%3)*8192*4);
        #pragma unroll
        for (int half = 0; half < 2; half++) {
            int w0 = half*8;
            uint32_t ah[2][4], al[2][4];
            #pragma unroll
            for (int mt = 0; mt < 2; mt++) {
                int r = wm*32 + mt*16 + aro;
                uint32_t ad = sb + stoff + (uint32_t)sww16(r, w0+awo)*4;
                LDSM4(ah[mt][0],ah[mt][1],ah[mt][2],ah[mt][3], ad);
                LDSM4(al[mt][0],al[mt][1],al[mt][2],al[mt][3], ad + 8192);
            }
            /* consume B fragments per ntp-pair: only 8 live B words */
            #pragma unroll
            for (int ntp = 0; ntp < 8; ntp += 2) {
                uint32_t bh[4], bl[4];
                int r = wn*64 + ntp*8 + bro;
                uint32_t ad = sb + stoff + 16384 + (uint32_t)sww16(r, w0+bwo)*4;
                LDSM4(bh[0],bh[1],bh[2],bh[3], ad);
                LDSM4(bl[0],bl[1],bl[2],bl[3], ad + 8192);
                #pragma unroll
                for (int j = 0; j < 2; j++) {
                    int nt = ntp + j;
                    #pragma unroll
                    for (int mt = 0; mt < 2; mt++) {
                        mma_bf16(acc[mt][nt], ah[mt], bh + 2*j);
                        mma_bf16(acc[mt][nt], ah[mt], bl + 2*j);
                        mma_bf16(acc[mt][nt], al[mt], bh + 2*j);
                    }
                }
            }
        }
        if (s + 2 < nk) { GISSUE(s+2); }
        CPCOMMIT();
    }

    #pragma unroll
    for (int mt = 0; mt < 2; mt++) {
        int rb0 = m0 + wm*32 + mt*16 + g4;
        #pragma unroll
        for (int h = 0; h < 2; h++) {
            int m = rb0 + h*8;
            #pragma unroll
            for (int nt = 0; nt < 8; nt++) {
                int nl = wn*64 + nt*8 + 2*t4;
                float2 a2 = make_float2(acc[mt][nt][2*h], acc[mt][nt][2*h+1]);
                if (EPI == 3) {
                    int ng = n0loc + nl;
                    if (ng < 1280) {
                        int t = m & (SEQL-1); int dp = (ng & 63) >> 1;
                        float c = bias0[t*32+dp], sn = bias1[t*32+dp];
                        float r0 = a2.x*c - a2.y*sn, r1 = a2.x*sn + a2.y*c;
                        a2.x = r0; a2.y = r1;
                    }
                    uint32_t hw = pack_hi(a2.x, a2.y);
                    uint32_t lw = pack_hi(a2.x-hi_part(a2.x), a2.y-hi_part(a2.y));
                    if (ng < 1024) {
                        g_qh[(size_t)m*512 + (ng>>1)] = hw;
                        g_ql[(size_t)m*512 + (ng>>1)] = lw;
                    } else if (ng < 1280) {
                        int c = (ng-1024)>>1;
                        g_kh[(size_t)m*128 + c] = hw;
                        g_kl[(size_t)m*128 + c] = lw;
                    } else {
                        int c = (ng-1280)>>1;
                        g_vh[(size_t)m*128 + c] = hw;
                        g_vl[(size_t)m*128 + c] = lw;
                    }
                } else {
                    float2 o;
                    if (EPI == 0) {
                        o = a2;
                    } else if (EPI == 1) {
                        const float2 bv = *(const float2*)(bias + n0loc + nl);
                        o.x = a2.x + bv.x; o.y = a2.y + bv.y;
                    } else {
                        int ng = n0loc + nl;
                        const float2 gv = *(const float2*)(mod + (size_t)(m>>3)*(3*DIMN) + goff + ng);
                        const float2 rv = *(const float2*)(resid + (size_t)m*ldr + ng);
                        o.x = rv.x + gv.x*a2.x;
                        o.y = rv.y + gv.y*a2.y;
                    }
                    *(float2*)(Cg + (size_t)m*ldc + nl) = o;
                }
            }
        }
    }
}

/* ---------------- fused weight convert ------------------------------------ */
__global__ __launch_bounds__(256) void conv_all(
    const float* __restrict__ wq, const float* __restrict__ wk,
    const float* __restrict__ wv, const float* __restrict__ wo,
    const float* __restrict__ w1, const float* __restrict__ w3,
    const float* __restrict__ w2, const float* __restrict__ maw,
    const float* __restrict__ mfw,
    bf16* __restrict__ wh, bf16* __restrict__ wl) {
    int bb = blockIdx.x;
    const float* src; int loc, dof;
    if      (bb < 1024)  { src = wq;  loc = bb;       dof = OWQ; }
    else if (bb < 1280)  { src = wk;  loc = bb-1024;  dof = OWK; }
    else if (bb < 1536)  { src = wv;  loc = bb-1280;  dof = OWV; }
    else if (bb < 2560)  { src = wo;  loc = bb-1536;  dof = OWO; }
    else if (bb < 3584)  { src = w1;  loc = bb-2560;  dof = OW1; }
    else if (bb < 4608)  { src = w3;  loc = bb-3584;  dof = OW3; }
    else if (bb < 5632)  { src = w2;  loc = bb-4608;  dof = OW2; }
    else if (bb < 8704)  { src = maw; loc = bb-5632;  dof = OMA; }
    else                 { src = mfw; loc = bb-8704;  dof = OMF; }
    int i = loc*256 + threadIdx.x;
    float4 v = ((const float4*)src)[i];
    ((uint2*)(wh + dof))[i] = make_uint2(pack_hi(v.x,v.y), pack_hi(v.z,v.w));
    float lx=v.x-hi_part(v.x), ly=v.y-hi_part(v.y);
    float lz=v.z-hi_part(v.z), lw=v.w-hi_part(v.w);
    ((uint2*)(wl + dof))[i] = make_uint2(pack_hi(lx,ly), pack_hi(lz,lw));
}

/* ---------------- elementwise kernels ------------------------------------ */
__global__ __launch_bounds__(256) void silu_kernel(
    const float* __restrict__ in, bf16* __restrict__ hi, bf16* __restrict__ lo) {
    int i = blockIdx.x * 256 + threadIdx.x;
    float4 v = ((const float4*)in)[i];
    float4 o;
    o.x = v.x / (1.f + __expf(-v.x));
    o.y = v.y / (1.f + __expf(-v.y));
    o.z = v.z / (1.f + __expf(-v.z));
    o.w = v.w / (1.f + __expf(-v.w));
    ((uint2*)hi)[i] = make_uint2(pack_hi(o.x,o.y), pack_hi(o.z,o.w));
    float lx=o.x-hi_part(o.x), ly=o.y-hi_part(o.y);
    float lz=o.z-hi_part(o.z), lw=o.w-hi_part(o.w);
    ((uint2*)lo)[i] = make_uint2(pack_hi(lx,ly), pack_hi(lz,lw));
}

__global__ __launch_bounds__(256) void swiglu_kernel(
    const float* __restrict__ g1, const float* __restrict__ g3,
    bf16* __restrict__ hi, bf16* __restrict__ lo) {
    int i = blockIdx.x * 256 + threadIdx.x;
    float4 a = ((const float4*)g1)[i];
    float4 b = ((const float4*)g3)[i];
    float4 o;
    o.x = (a.x / (1.f + __expf(-a.x))) * b.x;
    o.y = (a.y / (1.f + __expf(-a.y))) * b.y;
    o.z = (a.z / (1.f + __expf(-a.z))) * b.z;
    o.w = (a.w / (1.f + __expf(-a.w))) * b.w;
    ((uint2*)hi)[i] = make_uint2(pack_hi(o.x,o.y), pack_hi(o.z,o.w));
    float lx=o.x-hi_part(o.x), ly=o.y-hi_part(o.y);
    float lz=o.z-hi_part(o.z), lw=o.w-hi_part(o.w);
    ((uint2*)lo)[i] = make_uint2(pack_hi(lx,ly), pack_hi(lz,lw));
}

__global__ __launch_bounds__(256) void rmsnorm_mod_kernel(
    const float* __restrict__ X, const float* __restrict__ w,
    const float* __restrict__ mod, bf16* __restrict__ oh, bf16* __restrict__ ol) {
    int m = blockIdx.x;
    int tid = threadIdx.x;
    float4 v = ((const float4*)(X + (size_t)m*DIMN))[tid];
    float ss = v.x*v.x + v.y*v.y + v.z*v.z + v.w*v.w;
    #pragma unroll
    for (int o = 16; o; o >>= 1) ss += __shfl_xor_sync(0xffffffffu, ss, o);
    __shared__ float red[8];
    if ((tid & 31) == 0) red[tid >> 5] = ss;
    __syncthreads();
    float tot = red[0]+red[1]+red[2]+red[3]+red[4]+red[5]+red[6]+red[7];
    float rms = rsqrtf(tot * (1.f/DIMN) + EPSV);
    const float* mrow = mod + (size_t)(m >> 3) * (3*DIMN);
    float4 sh = *(const float4*)(mrow + tid*4);
    float4 sc = *(const float4*)(mrow + DIMN + tid*4);
    float4 wv = ((const float4*)w)[tid];
    float4 o;
    o.x = v.x*rms*wv.x*(1.f+sc.x) + sh.x;
    o.y = v.y*rms*wv.y*(1.f+sc.y) + sh.y;
    o.z = v.z*rms*wv.z*(1.f+sc.z) + sh.z;
    o.w = v.w*rms*wv.w*(1.f+sc.w) + sh.w;
    ((uint2*)(oh + (size_t)m*DIMN))[tid] = make_uint2(pack_hi(o.x,o.y), pack_hi(o.z,o.w));
    float lx=o.x-hi_part(o.x), ly=o.y-hi_part(o.y);
    float lz=o.z-hi_part(o.z), lw=o.w-hi_part(o.w);
    ((uint2*)(ol + (size_t)m*DIMN))[tid] = make_uint2(pack_hi(lx,ly), pack_hi(lz,lw));
}

/* ---------------- mma block-causal flash attention ------------------------ */
/* CTA: 128 q-rows, 1 head, 1 batch. 8 warps x 16 rows. cp.async + ldmatrix. */
/* smem words: Qh[0) Ql[4096) Kh[8192) Kl[10240) Vh[12288) Vl[14336)         */
#define ATT_SMEM 65536

__global__ __launch_bounds__(256, 2) void attn_kernel(
    bf16* __restrict__ outh, bf16* __restrict__ outl) {
    extern __shared__ uint32_t sm[];
    int qt2 = blockIdx.x, h = blockIdx.y, b = blockIdx.z;
    int tid = threadIdx.x, lane = tid & 31, wid = tid >> 5;
    int g4 = lane >> 2, t4 = lane & 3;
    int lr = lane & 7, sel = lane >> 3;
    int aro = (sel & 1)*8 + lr, awo = (sel >> 1)*4;
    int bro = (sel >> 1)*8 + lr, bwo = (sel & 1)*4;
    int vro = (sel & 1)*8 + lr, vwo = (sel >> 1)*4;
    uint32_t sb = smem_u32(sm);

    /* async-load Q (128 rows x 32 words) hi+lo */
    {
        const uint32_t* qs  = g_qh + (size_t)(b*SEQL + qt2*128)*512 + h*32;
        const uint32_t* qsl = g_ql + (size_t)(b*SEQL + qt2*128)*512 + h*32;
        #pragma unroll
        for (int i = 0; i < 4; i++) {
            int id = tid + i*256;
            int r = id >> 3, ch = (id & 7)*4;
            uint32_t d = (uint32_t)sww32(r, ch)*4;
            CPA16(sb + d,         qs  + (size_t)r*512 + ch);
            CPA16(sb + 16384 + d, qsl + (size_t)r*512 + ch);
        }
    }

    int kmax = 2*qt2 + (wid >> 2);
    int rb01 = (wid & 3)*2, rb23 = rb01 + 1;
    int base_r = wid*16;
    float s[8][4], o[8][4];
    float m0 = -1e30f, m1 = -1e30f, l0 = 0.f, l1 = 0.f;
    #pragma unroll
    for (int nt=0;nt<8;nt++)
        #pragma unroll
        for (int e=0;e<4;e++) o[nt][e]=0.f;

    int ktend = 2*qt2 + 1;
    for (int kt = 0; kt <= ktend; kt++) {
        __syncthreads();
        /* async-load K and V tiles (64 x 32 words) hi+lo */
        {
            size_t rowb = (size_t)(b*SEQL + kt*64)*128 + (h>>2)*32;
            #pragma unroll
            for (int i = 0; i < 2; i++) {
                int id = tid + i*256;
                int r = id >> 3, ch = (id & 7)*4;
                uint32_t d = (uint32_t)sww32(r, ch)*4;
                size_t src = rowb + (size_t)r*128 + ch;
                CPA16(sb + 32768 + d, g_kh + src);
                CPA16(sb + 40960 + d, g_kl + src);
                CPA16(sb + 49152 + d, g_vh + src);
                CPA16(sb + 57344 + d, g_vl + src);
            }
        }
        CPCOMMIT(); CPWAIT0();
        __syncthreads();
        if (kt > kmax) continue;

        /* S = Q @ K^T (split bf16, ldmatrix, per-pair consume) */
        #pragma unroll
        for (int nt=0;nt<8;nt++)
            #pragma unroll
            for (int e=0;e<4;e++) s[nt][e]=0.f;
        #pragma unroll
        for (int ks = 0; ks < 4; ks++) {
            int w0 = ks*8;
            uint32_t ah[4], al[4];
            {
                int r = base_r + aro;
                uint32_t ad = sb + (uint32_t)sww32(r, w0+awo)*4;
                LDSM4(ah[0],ah[1],ah[2],ah[3], ad);
                LDSM4(al[0],al[1],al[2],al[3], ad + 16384);
            }
            #pragma unroll
            for (int ntp = 0; ntp < 8; ntp += 2) {
                uint32_t bh[4], bl[4];
                int r = ntp*8 + bro;
                uint32_t ad = sb + 32768 + (uint32_t)sww32(r, w0+bwo)*4;
                LDSM4(bh[0],bh[1],bh[2],bh[3], ad);
                LDSM4(bl[0],bl[1],bl[2],bl[3], ad + 8192);
                #pragma unroll
                for (int j = 0; j < 2; j++) {
                    mma_bf16(s[ntp+j], ah, bh + 2*j);
                    mma_bf16(s[ntp+j], ah, bl + 2*j);
                    mma_bf16(s[ntp+j], al, bh + 2*j);
                }
            }
        }
        #pragma unroll
        for (int nt=0;nt<8;nt++)
            #pragma unroll
            for (int e=0;e<4;e++) s[nt][e] *= 0.125f;
        if (kt == kmax) {
            #pragma unroll
            for (int nt=0;nt<8;nt++) {
                if (nt > rb01) { s[nt][0] = -1e30f; s[nt][1] = -1e30f; }
                if (nt > rb23) { s[nt][2] = -1e30f; s[nt][3] = -1e30f; }
            }
        }
        /* online softmax */
        float mx0 = -1e30f, mx1 = -1e30f;
        #pragma unroll
        for (int nt=0;nt<8;nt++) {
            mx0 = fmaxf(mx0, fmaxf(s[nt][0], s[nt][1]));
            mx1 = fmaxf(mx1, fmaxf(s[nt][2], s[nt][3]));
        }
        mx0 = fmaxf(mx0, __shfl_xor_sync(0xffffffffu, mx0, 1));
        mx0 = fmaxf(mx0, __shfl_xor_sync(0xffffffffu, mx0, 2));
        mx1 = fmaxf(mx1, __shfl_xor_sync(0xffffffffu, mx1, 1));
        mx1 = fmaxf(mx1, __shfl_xor_sync(0xffffffffu, mx1, 2));
        float nm0 = fmaxf(m0, mx0), nm1 = fmaxf(m1, mx1);
        float al0 = fexp(m0 - nm0), al1 = fexp(m1 - nm1);
        m0 = nm0; m1 = nm1;
        float sum0 = 0.f, sum1 = 0.f;
        #pragma unroll
        for (int nt=0;nt<8;nt++) {
            s[nt][0] = fexp(s[nt][0] - m0);
            s[nt][1] = fexp(s[nt][1] - m0);
            s[nt][2] = fexp(s[nt][2] - m1);
            s[nt][3] = fexp(s[nt][3] - m1);
            sum0 += s[nt][0] + s[nt][1];
            sum1 += s[nt][2] + s[nt][3];
        }
        sum0 += __shfl_xor_sync(0xffffffffu, sum0, 1);
        sum0 += __shfl_xor_sync(0xffffffffu, sum0, 2);
        sum1 += __shfl_xor_sync(0xffffffffu, sum1, 1);
        sum1 += __shfl_xor_sync(0xffffffffu, sum1, 2);
        l0 = l0*al0 + sum0;
        l1 = l1*al1 + sum1;
        #pragma unroll
        for (int nt=0;nt<8;nt++) {
            o[nt][0] *= al0; o[nt][1] *= al0;
            o[nt][2] *= al1; o[nt][3] *= al1;
        }
        /* O += P @ V (V^T via ldmatrix.trans, per-pair consume) */
        #pragma unroll
        for (int ks = 0; ks < 4; ks++) {
            uint32_t ph[4], pl[4];
            ph[0] = pack_hi(s[2*ks][0],   s[2*ks][1]);
            ph[1] = pack_hi(s[2*ks][2],   s[2*ks][3]);
            ph[2] = pack_hi(s[2*ks+1][0], s[2*ks+1][1]);
            ph[3] = pack_hi(s[2*ks+1][2], s[2*ks+1][3]);
            pl[0] = pack_hi(s[2*ks][0]-hi_part(s[2*ks][0]),
                            s[2*ks][1]-hi_part(s[2*ks][1]));
            pl[1] = pack_hi(s[2*ks][2]-hi_part(s[2*ks][2]),
                            s[2*ks][3]-hi_part(s[2*ks][3]));
            pl[2] = pack_hi(s[2*ks+1][0]-hi_part(s[2*ks+1][0]),
                            s[2*ks+1][1]-hi_part(s[2*ks+1][1]));
            pl[3] = pack_hi(s[2*ks+1][2]-hi_part(s[2*ks+1][2]),
                            s[2*ks+1][3]-hi_part(s[2*ks+1][3]));
            #pragma unroll
            for (int ntp = 0; ntp < 8; ntp += 2) {
                uint32_t bh[4], bl[4];
                int rt = ks*16 + vro;
                uint32_t ad = sb + 49152 +
                    (uint32_t)sww32(rt, ntp*4 + vwo)*4;
                LDSM4T(bh[0],bh[1],bh[2],bh[3], ad);
                LDSM4T(bl[0],bl[1],bl[2],bl[3], ad + 8192);
                #pragma unroll
                for (int j = 0; j < 2; j++) {
                    mma_bf16(o[ntp+j], ph, bh + 2*j);
                    mma_bf16(o[ntp+j], ph, bl + 2*j);
                    mma_bf16(o[ntp+j], pl, bh + 2*j);
                }
            }
        }
    }

    /* normalize and write bf16 hi/lo */
    float i0 = 1.f / l0, i1 = 1.f / l1;
    int tok0 = b*SEQL + qt2*128 + base_r + g4;
    #pragma unroll
    for (int nt = 0; nt < 8; nt++) {
        int col = h*64 + nt*8 + 2*t4;
        float x0 = o[nt][0]*i0, x1 = o[nt][1]*i0;
        float x2 = o[nt][2]*i1, x3 = o[nt][3]*i1;
        ((uint32_t*)outh)[((size_t)tok0*DIMN + col) >> 1] = pack_hi(x0, x1);
        ((uint32_t*)outl)[((size_t)tok0*DIMN + col) >> 1] =
            pack_hi(x0-hi_part(x0), x1-hi_part(x1));
        ((uint32_t*)outh)[((size_t)(tok0+8)*DIMN + col) >> 1] = pack_hi(x2, x3);
        ((uint32_t*)outl)[((size_t)(tok0+8)*DIMN + col) >> 1] =
            pack_hi(x2-hi_part(x2), x3-hi_part(x3));
    }
}

/* ---------------- host launcher ------------------------------------------ */
extern "C" void kernel_launch(void* const* d_in, const int* in_sizes, int n_in,
                              void* d_out, int out_size) {
    const float *x,*vec,*wq,*wk,*wv,*wo,*w1,*w2,*w3,*maw,*mab,*mfw,*mfb,*n1,*n2,*fc,*fs;
    if (in_sizes[2] == 32768) {                   /* reference-argument order */
        x  =(const float*)d_in[0];  vec=(const float*)d_in[1];
        fc =(const float*)d_in[2];  fs =(const float*)d_in[3];
        wq =(const float*)d_in[4];  wk =(const float*)d_in[5];
        wv =(const float*)d_in[6];  wo =(const float*)d_in[7];
        w1 =(const float*)d_in[8];  w2 =(const float*)d_in[9];
        w3 =(const float*)d_in[10];
        maw=(const float*)d_in[11]; mab=(const float*)d_in[12];
        mfw=(const float*)d_in[13]; mfb=(const float*)d_in[14];
        n1 =(const float*)d_in[15]; n2 =(const float*)d_in[16];
    } else {                                      /* setup_inputs dict order */
        x  =(const float*)d_in[0];  vec=(const float*)d_in[1];
        wq =(const float*)d_in[2];  wk =(const float*)d_in[3];
        wv =(const float*)d_in[4];  wo =(const float*)d_in[5];
        w1 =(const float*)d_in[6];  w2 =(const float*)d_in[7];
        w3 =(const float*)d_in[8];
        maw=(const float*)d_in[9];  mab=(const float*)d_in[10];
        mfw=(const float*)d_in[11]; mfb=(const float*)d_in[12];
        n1 =(const float*)d_in[13]; n2 =(const float*)d_in[14];
        fc =(const float*)d_in[15]; fs =(const float*)d_in[16];
    }
    float* out = (float*)d_out;

    float *p_ma,*p_mf,*p_h,*p_g1,*p_g3;
    bf16 *p_svh,*p_svl,*p_xnh,*p_xnl,*p_hnh,*p_hnl,*p_ath,*p_atl,*p_g1h,*p_g1l,*p_wh,*p_wl;
    cudaGetSymbolAddress((void**)&p_ma,  g_mod_a);
    cudaGetSymbolAddress((void**)&p_mf,  g_mod_f);
    cudaGetSymbolAddress((void**)&p_h,   g_h);
    cudaGetSymbolAddress((void**)&p_g1,  g_g1);
    cudaGetSymbolAddress((void**)&p_g3,  g_g3);
    cudaGetSymbolAddress((void**)&p_svh, g_svh);
    cudaGetSymbolAddress((void**)&p_svl, g_svl);
    cudaGetSymbolAddress((void**)&p_xnh, g_xnh);
    cudaGetSymbolAddress((void**)&p_xnl, g_xnl);
    cudaGetSymbolAddress((void**)&p_hnh, g_hnh);
    cudaGetSymbolAddress((void**)&p_hnl, g_hnl);
    cudaGetSymbolAddress((void**)&p_ath, g_ath);
    cudaGetSymbolAddress((void**)&p_atl, g_atl);
    cudaGetSymbolAddress((void**)&p_g1h, g_g1h);
    cudaGetSymbolAddress((void**)&p_g1l, g_g1l);
    cudaGetSymbolAddress((void**)&p_wh,  g_wh);
    cudaGetSymbolAddress((void**)&p_wl,  g_wl);

    cudaFuncSetAttribute(attn_kernel,
                         cudaFuncAttributeMaxDynamicSharedMemorySize, ATT_SMEM);
    cudaFuncSetAttribute(gemm_bf<1,2>,
                         cudaFuncAttributeMaxDynamicSharedMemorySize, GSMEM);
    cudaFuncSetAttribute(gemm_bf<3,1>,
                         cudaFuncAttributeMaxDynamicSharedMemorySize, GSMEM);
    cudaFuncSetAttribute(gemm_bf<0,2>,
                         cudaFuncAttributeMaxDynamicSharedMemorySize, GSMEM);
    cudaFuncSetAttribute(gemm_bf<2,0>,
                         cudaFuncAttributeMaxDynamicSharedMemorySize, GSMEM);

    /* 0. all weight converts in one launch */
    conv_all<<<11776, 256>>>(wq, wk, wv, wo, w1, w3, w2, maw, mfw, p_wh, p_wl);

    /* 1. silu(vec) -> hi/lo */
    silu_kernel<<<512, 256>>>(vec, p_svh, p_svl);

    /* 2. both modulation GEMMs in one launch */
    gemm_bf<1,2><<<dim3(48,4), 256, GSMEM>>>(
        p_svh,p_svl, p_wh+OMA,p_wl+OMA, p_wh+OMF,p_wl+OMF, nullptr,nullptr,
        p_ma,p_mf,3*DIMN, DIMN, 24, mab,mfb, nullptr,0, nullptr,0);

    /* 3. xn -> hi/lo */
    rmsnorm_mod_kernel<<<NTOK, 256>>>(x, n1, p_ma, p_xnh, p_xnl);

    /* 4. QKV + fused RoPE -> q/k/v hi/lo buffers */
    gemm_bf<3,1><<<dim3(12,32), 256, GSMEM>>>(
        p_xnh,p_xnl, p_wh+OWQ,p_wl+OWQ, p_wh+OWK,p_wl+OWK, p_wh+OWV,p_wl+OWV,
        nullptr,nullptr,0, DIMN, 0, fc,fs, nullptr,0, nullptr,0);

    /* 5. mma block-causal attention -> hi/lo */
    attn_kernel<<<dim3(8,16,BATCHN), 256, ATT_SMEM>>>(p_ath, p_atl);

    /* 6. h = x + gate_a * (attn @ wo^T) */
    gemm_bf<2,0><<<dim3(8,32), 256, GSMEM>>>(
        p_ath,p_atl, p_wh+OWO,p_wl+OWO, nullptr,nullptr, nullptr,nullptr,
        p_h,nullptr,DIMN, DIMN, 0, nullptr,nullptr, x,DIMN, p_ma, 2*DIMN);

    /* 7. hn -> hi/lo */
    rmsnorm_mod_kernel<<<NTOK, 256>>>(p_h, n2, p_mf, p_hnh, p_hnl);

    /* 8. FFN up: w1 + w3 in one launch */
    gemm_bf<0,2><<<dim3(16,32), 256, GSMEM>>>(
        p_hnh,p_hnl, p_wh+OW1,p_wl+OW1, p_wh+OW3,p_wl+OW3, nullptr,nullptr,
        p_g1,p_g3,DIMN, DIMN, 8, nullptr,nullptr, nullptr,0, nullptr,0);

    /* 9. swiglu -> hi/lo */
    swiglu_kernel<<<4096, 256>>>(p_g1, p_g3, p_g1h, p_g1l);

    /* 10. out = h + gate_f * (swiglu @ w2^T) */
    gemm_bf<2,0><<<dim3(8,32), 256, GSMEM>>>(
        p_g1h,p_g1l, p_wh+OW2,p_wl+OW2, nullptr,nullptr, nullptr,nullptr,
        out,nullptr,DIMN, DIMN, 0, nullptr,nullptr, p_h,DIMN, p_mf, 2*DIMN);
}

// round 13
// speedup vs baseline: 1.5034x; 1.0123x over previous
#include <cuda_runtime.h>
#include <cuda_bf16.h>
#include <math.h>
#include <stdint.h>

#define DIMN   1024
#define SEQL   1024
#define BATCHN 4
#define NTOK   (BATCHN*SEQL)     /* 4096 */
#define NBLK   (BATCHN*128)      /* 512 tokens of vec */
#define EPSV   1e-6f

typedef __nv_bfloat16 bf16;

/* ---------------- scratch (device globals: no allocation allowed) -------- */
__device__ float g_mod_a[NBLK*3*DIMN];
__device__ float g_mod_f[NBLK*3*DIMN];
__device__ float g_h[NTOK*DIMN];
/* bf16 hi/lo activation buffers */
__device__ bf16 g_svh[NBLK*DIMN],  g_svl[NBLK*DIMN];
__device__ bf16 g_xnh[NTOK*DIMN],  g_xnl[NTOK*DIMN];
__device__ bf16 g_hnh[NTOK*DIMN],  g_hnl[NTOK*DIMN];
__device__ bf16 g_ath[NTOK*DIMN],  g_atl[NTOK*DIMN];
__device__ bf16 g_g1h[NTOK*DIMN],  g_g1l[NTOK*DIMN];
/* rope'd Q/K and V as packed bf16x2 words, hi and lo */
__device__ uint32_t g_qh[NTOK*512], g_ql[NTOK*512];
__device__ uint32_t g_kh[NTOK*128], g_kl[NTOK*128];
__device__ uint32_t g_vh[NTOK*128], g_vl[NTOK*128];
/* weight hi/lo pool */
#define OWQ  0
#define OWK  1048576
#define OWV  1310720
#define OWO  1572864
#define OW1  2621440
#define OW3  3670016
#define OW2  4718592
#define OMA  5767168
#define OMF  8912896
#define WPOOL 12058624
__device__ bf16 g_wh[WPOOL], g_wl[WPOOL];

/* ---------------- helpers ------------------------------------------------ */
__device__ __forceinline__ uint32_t pack_hi(float x, float y) {
    return __byte_perm(__float_as_uint(x), __float_as_uint(y), 0x7632);
}
__device__ __forceinline__ float hi_part(float x) {
    return __uint_as_float(__float_as_uint(x) & 0xFFFF0000u);
}
__device__ __forceinline__ uint32_t smem_u32(const void* p) {
    uint32_t a;
    asm("{ .reg .u64 t; cvta.to.shared.u64 t, %1; cvt.u32.u64 %0, t; }"
        : "=r"(a) : "l"(p));
    return a;
}
__device__ __forceinline__ int sww16(int r, int w) {
    return r*16 + (w ^ (((r >> 1) & 3) << 2));
}
__device__ __forceinline__ int sww32(int r, int w) {
    return r*32 + (w ^ ((r & 7) << 2));
}
__device__ __forceinline__ void mma_bf16(float* c, const uint32_t* a,
                                         const uint32_t* b) {
    asm volatile(
        "mma.sync.aligned.m16n8k16.row.col.f32.bf16.bf16.f32 "
        "{%0,%1,%2,%3}, {%4,%5,%6,%7}, {%8,%9}, {%0,%1,%2,%3};"
        : "+f"(c[0]), "+f"(c[1]), "+f"(c[2]), "+f"(c[3])
        : "r"(a[0]), "r"(a[1]), "r"(a[2]), "r"(a[3]), "r"(b[0]), "r"(b[1]));
}
#define LDSM4(r0,r1,r2,r3, a) \
    asm volatile("ldmatrix.sync.aligned.m8n8.x4.shared.b16 {%0,%1,%2,%3}, [%4];" \
        : "=r"(r0),"=r"(r1),"=r"(r2),"=r"(r3) : "r"(a))
#define LDSM4T(r0,r1,r2,r3, a) \
    asm volatile("ldmatrix.sync.aligned.m8n8.x4.trans.shared.b16 {%0,%1,%2,%3}, [%4];" \
        : "=r"(r0),"=r"(r1),"=r"(r2),"=r"(r3) : "r"(a))
#define CPA16(dst, src) \
    asm volatile("cp.async.cg.shared.global [%0], [%1], 16;" \
        :: "r"(dst), "l"(src) : "memory")
#define CPCOMMIT() asm volatile("cp.async.commit_group;" ::: "memory")
/* fast exp on FMA pipe */
__device__ __forceinline__ float fexp(float x) {
    float t = fmaxf(x * 1.44269504f, -126.f);
    float fi = floorf(t);
    float f = t - fi;
    float p = fmaf(f, 0.00133336f, 0.00961812f);
    p = fmaf(f, p, 0.05550411f);
    p = fmaf(f, p, 0.24022651f);
    p = fmaf(f, p, 0.69314718f);
    p = fmaf(f, p, 1.0f);
    return __int_as_float(((int)fi + 127) << 23) * p;
}

/* ------------- split-bf16 GEMM via cp.async + ldmatrix -------------------- */
#define GSMEM 98304

#define GISSUE(s_) do {                                                        \
    int kof = (s_)*32;                                                         \
    _Pragma("unroll")                                                          \
    for (int i = 0; i < 8; i++) {                                              \
        int id = tid + i*256;                                                  \
        int part = id >> 9, loc = id & 511;                                    \
        int row = loc >> 2, ch = loc & 3;                                      \
        const bf16* src;                                                       \
        if (MODE == 3 && part >= 2) {                                          \
            int nlog = (row >> 4)*8 + (row & 7);                               \
            const bf16* wsel = (part==2) ? ((row & 8) ? srcB3h : srcBh)        \
                                         : ((row & 8) ? srcB3l : srcBl);       \
            src = wsel + (size_t)nlog*K + kof + ch*8;                          \
        } else {                                                               \
            const bf16* sp = (part==0) ? srcAh : (part==1) ? srcAl             \
                           : (part==2) ? srcBh : srcBl;                        \
            src = sp + (size_t)row*K + kof + ch*8;                             \
        }                                                                      \
        uint32_t dst = sb + (uint32_t)((((s_)%3)*8192 + part*2048              \
                       + sww16(row, ch*4)) * 4);                               \
        CPA16(dst, src);                                                       \
    }                                                                          \
} while (0)

/* MODE 0: single B/C. MODE 1: qkv (3 Bs). MODE 2: dual B/C split by bx.
   MODE 3: FFN w1/w3 interleaved, swiglu epilogue -> bf16 hi/lo (EPI 4).     */
/* EPI 0: C=acc; 1: +bias; 2: resid+mod*acc; 3: rope->q/k/v; 4: swiglu.      */
template<int EPI, int MODE>
__global__ __launch_bounds__(256, 2) void gemm_bf(
    const bf16* __restrict__ Ah, const bf16* __restrict__ Al,
    const bf16* __restrict__ Bh0, const bf16* __restrict__ Bl0,
    const bf16* __restrict__ Bh1, const bf16* __restrict__ Bl1,
    const bf16* __restrict__ Bh2, const bf16* __restrict__ Bl2,
    float* __restrict__ C0, float* __restrict__ C1, int ldc,
    int K, int split,
    const float* __restrict__ bias0, const float* __restrict__ bias1,
    const float* __restrict__ resid, int ldr,
    const float* __restrict__ mod, int goff) {
    extern __shared__ uint32_t swm[];
    int tid = threadIdx.x, lane = tid & 31, wid = tid >> 5;
    int wm = wid >> 1, wn = wid & 1;
    int g4 = lane >> 2, t4 = lane & 3;
    int lr = lane & 7, sel = lane >> 3;
    int aro = (sel & 1)*8 + lr, awo = (sel >> 1)*4;
    int bro = (sel >> 1)*8 + lr, bwo = (sel & 1)*4;
    int bx = blockIdx.x, m0 = blockIdx.y*128;
    int n0glob = bx*128;

    const bf16 *Bh, *Bl, *B3h = nullptr, *B3l = nullptr;
    float* Cg = nullptr; const float* bias = nullptr;
    int n0loc, row0;
    if (MODE == 0) {
        Bh = Bh0; Bl = Bl0; row0 = n0glob; Cg = C0 + n0glob;
        bias = bias0; n0loc = n0glob;
    } else if (MODE == 1) {
        if (n0glob < 1024)      { Bh = Bh0; Bl = Bl0; row0 = n0glob; }
        else if (n0glob < 1280) { Bh = Bh1; Bl = Bl1; row0 = n0glob-1024; }
        else                    { Bh = Bh2; Bl = Bl2; row0 = n0glob-1280; }
        n0loc = n0glob;
    } else if (MODE == 2) {
        int sel2 = bx >= split; int nb = bx - (sel2 ? split : 0);
        n0loc = nb*128; row0 = n0loc;
        Bh = sel2 ? Bh1 : Bh0;  Bl = sel2 ? Bl1 : Bl0;
        Cg = (sel2 ? C1 : C0) + n0loc;
        bias = sel2 ? bias1 : bias0;
    } else {   /* MODE 3: w1/w3 interleaved, 64 output cols per CTA */
        row0 = bx*64; n0loc = bx*64;
        Bh = Bh0; Bl = Bl0; B3h = Bh1; B3l = Bl1;
    }
    const bf16* srcAh = Ah + (size_t)m0*K;
    const bf16* srcAl = Al + (size_t)m0*K;
    const bf16* srcBh = Bh + (size_t)row0*K;
    const bf16* srcBl = Bl + (size_t)row0*K;
    const bf16* srcB3h = (MODE == 3) ? B3h + (size_t)row0*K : srcBh;
    const bf16* srcB3l = (MODE == 3) ? B3l + (size_t)row0*K : srcBl;
    uint32_t sb = smem_u32(swm);

    int nk = K >> 5;
    GISSUE(0);
    CPCOMMIT();
    GISSUE(1);
    CPCOMMIT();

    float acc[2][8][4];
    #pragma unroll
    for (int mt=0;mt<2;mt++)
        #pragma unroll
        for (int nt=0;nt<8;nt++)
            #pragma unroll
            for (int e=0;e<4;e++) acc[mt][nt][e]=0.f;

    for (int s = 0; s < nk; s++) {
        asm volatile("cp.async.wait_group 1;" ::: "memory");
        __syncthreads();
        uint32_t stoff = (uint32_t)((s%3)*8192*4);
        #pragma unroll
        for (int half = 0; half < 2; half++) {
            int w0 = half*8;
            uint32_t ah[2][4], al[2][4];
            #pragma unroll
            for (int mt = 0; mt < 2; mt++) {
                int r = wm*32 + mt*16 + aro;
                uint32_t ad = sb + stoff + (uint32_t)sww16(r, w0+awo)*4;
                LDSM4(ah[mt][0],ah[mt][1],ah[mt][2],ah[mt][3], ad);
                LDSM4(al[mt][0],al[mt][1],al[mt][2],al[mt][3], ad + 8192);
            }
            #pragma unroll
            for (int ntp = 0; ntp < 8; ntp += 2) {
                uint32_t bh[4], bl[4];
                int r = wn*64 + ntp*8 + bro;
                uint32_t ad = sb + stoff + 16384 + (uint32_t)sww16(r, w0+bwo)*4;
                LDSM4(bh[0],bh[1],bh[2],bh[3], ad);
                LDSM4(bl[0],bl[1],bl[2],bl[3], ad + 8192);
                #pragma unroll
                for (int j = 0; j < 2; j++) {
                    int nt = ntp + j;
                    #pragma unroll
                    for (int mt = 0; mt < 2; mt++) {
                        mma_bf16(acc[mt][nt], ah[mt], bh + 2*j);
                        mma_bf16(acc[mt][nt], ah[mt], bl + 2*j);
                        mma_bf16(acc[mt][nt], al[mt], bh + 2*j);
                    }
                }
            }
        }
        if (s + 2 < nk) { GISSUE(s+2); }
        CPCOMMIT();
    }

    if (EPI == 4) {
        /* swiglu epilogue: pair (ntp even = g1, ntp+1 = g3), write bf16 */
        uint32_t* oh = (uint32_t*)C0;
        uint32_t* ol = (uint32_t*)C1;
        #pragma unroll
        for (int mt = 0; mt < 2; mt++) {
            int rb0 = m0 + wm*32 + mt*16 + g4;
            #pragma unroll
            for (int h = 0; h < 2; h++) {
                int m = rb0 + h*8;
                #pragma unroll
                for (int ntp = 0; ntp < 8; ntp += 2) {
                    int col = n0loc + wn*32 + (ntp>>1)*8 + 2*t4;
                    float gA = acc[mt][ntp][2*h],   gB = acc[mt][ntp][2*h+1];
                    float uA = acc[mt][ntp+1][2*h], uB = acc[mt][ntp+1][2*h+1];
                    float x0 = gA / (1.f + fexp(-gA)) * uA;
                    float x1 = gB / (1.f + fexp(-gB)) * uB;
                    size_t w = ((size_t)m*DIMN + col) >> 1;
                    oh[w] = pack_hi(x0, x1);
                    ol[w] = pack_hi(x0-hi_part(x0), x1-hi_part(x1));
                }
            }
        }
        return;
    }

    #pragma unroll
    for (int mt = 0; mt < 2; mt++) {
        int rb0 = m0 + wm*32 + mt*16 + g4;
        #pragma unroll
        for (int h = 0; h < 2; h++) {
            int m = rb0 + h*8;
            #pragma unroll
            for (int nt = 0; nt < 8; nt++) {
                int nl = wn*64 + nt*8 + 2*t4;
                float2 a2 = make_float2(acc[mt][nt][2*h], acc[mt][nt][2*h+1]);
                if (EPI == 3) {
                    int ng = n0loc + nl;
                    if (ng < 1280) {
                        int t = m & (SEQL-1); int dp = (ng & 63) >> 1;
                        float c = bias0[t*32+dp], sn = bias1[t*32+dp];
                        float r0 = a2.x*c - a2.y*sn, r1 = a2.x*sn + a2.y*c;
                        a2.x = r0; a2.y = r1;
                    }
                    uint32_t hw = pack_hi(a2.x, a2.y);
                    uint32_t lw = pack_hi(a2.x-hi_part(a2.x), a2.y-hi_part(a2.y));
                    if (ng < 1024) {
                        g_qh[(size_t)m*512 + (ng>>1)] = hw;
                        g_ql[(size_t)m*512 + (ng>>1)] = lw;
                    } else if (ng < 1280) {
                        int c = (ng-1024)>>1;
                        g_kh[(size_t)m*128 + c] = hw;
                        g_kl[(size_t)m*128 + c] = lw;
                    } else {
                        int c = (ng-1280)>>1;
                        g_vh[(size_t)m*128 + c] = hw;
                        g_vl[(size_t)m*128 + c] = lw;
                    }
                } else {
                    float2 o;
                    if (EPI == 0) {
                        o = a2;
                    } else if (EPI == 1) {
                        const float2 bv = *(const float2*)(bias + n0loc + nl);
                        o.x = a2.x + bv.x; o.y = a2.y + bv.y;
                    } else {
                        int ng = n0loc + nl;
                        const float2 gv = *(const float2*)(mod + (size_t)(m>>3)*(3*DIMN) + goff + ng);
                        const float2 rv = *(const float2*)(resid + (size_t)m*ldr + ng);
                        o.x = rv.x + gv.x*a2.x;
                        o.y = rv.y + gv.y*a2.y;
                    }
                    *(float2*)(Cg + (size_t)m*ldc + nl) = o;
                }
            }
        }
    }
}

/* -------- fused weight convert + silu(vec) (one launch) ------------------ */
__global__ __launch_bounds__(256) void conv_all(
    const float* __restrict__ wq, const float* __restrict__ wk,
    const float* __restrict__ wv, const float* __restrict__ wo,
    const float* __restrict__ w1, const float* __restrict__ w3,
    const float* __restrict__ w2, const float* __restrict__ maw,
    const float* __restrict__ mfw,
    bf16* __restrict__ wh, bf16* __restrict__ wl,
    const float* __restrict__ vec,
    bf16* __restrict__ svh, bf16* __restrict__ svl) {
    int bb = blockIdx.x;
    if (bb >= 11776) {    /* silu(vec) tail blocks */
        int i = (bb - 11776)*256 + threadIdx.x;
        float4 v = ((const float4*)vec)[i];
        float4 o;
        o.x = v.x / (1.f + __expf(-v.x));
        o.y = v.y / (1.f + __expf(-v.y));
        o.z = v.z / (1.f + __expf(-v.z));
        o.w = v.w / (1.f + __expf(-v.w));
        ((uint2*)svh)[i] = make_uint2(pack_hi(o.x,o.y), pack_hi(o.z,o.w));
        float lx=o.x-hi_part(o.x), ly=o.y-hi_part(o.y);
        float lz=o.z-hi_part(o.z), lw=o.w-hi_part(o.w);
        ((uint2*)svl)[i] = make_uint2(pack_hi(lx,ly), pack_hi(lz,lw));
        return;
    }
    const float* src; int loc, dof;
    if      (bb < 1024)  { src = wq;  loc = bb;       dof = OWQ; }
    else if (bb < 1280)  { src = wk;  loc = bb-1024;  dof = OWK; }
    else if (bb < 1536)  { src = wv;  loc = bb-1280;  dof = OWV; }
    else if (bb < 2560)  { src = wo;  loc = bb-1536;  dof = OWO; }
    else if (bb < 3584)  { src = w1;  loc = bb-2560;  dof = OW1; }
    else if (bb < 4608)  { src = w3;  loc = bb-3584;  dof = OW3; }
    else if (bb < 5632)  { src = w2;  loc = bb-4608;  dof = OW2; }
    else if (bb < 8704)  { src = maw; loc = bb-5632;  dof = OMA; }
    else                 { src = mfw; loc = bb-8704;  dof = OMF; }
    int i = loc*256 + threadIdx.x;
    float4 v = ((const float4*)src)[i];
    ((uint2*)(wh + dof))[i] = make_uint2(pack_hi(v.x,v.y), pack_hi(v.z,v.w));
    float lx=v.x-hi_part(v.x), ly=v.y-hi_part(v.y);
    float lz=v.z-hi_part(v.z), lw=v.w-hi_part(v.w);
    ((uint2*)(wl + dof))[i] = make_uint2(pack_hi(lx,ly), pack_hi(lz,lw));
}

/* ---------------- rmsnorm + modulate -> bf16 hi/lo ----------------------- */
__global__ __launch_bounds__(256) void rmsnorm_mod_kernel(
    const float* __restrict__ X, const float* __restrict__ w,
    const float* __restrict__ mod, bf16* __restrict__ oh, bf16* __restrict__ ol) {
    int m = blockIdx.x;
    int tid = threadIdx.x;
    float4 v = ((const float4*)(X + (size_t)m*DIMN))[tid];
    float ss = v.x*v.x + v.y*v.y + v.z*v.z + v.w*v.w;
    #pragma unroll
    for (int o = 16; o; o >>= 1) ss += __shfl_xor_sync(0xffffffffu, ss, o);
    __shared__ float red[8];
    if ((tid & 31) == 0) red[tid >> 5] = ss;
    __syncthreads();
    float tot = red[0]+red[1]+red[2]+red[3]+red[4]+red[5]+red[6]+red[7];
    float rms = rsqrtf(tot * (1.f/DIMN) + EPSV);
    const float* mrow = mod + (size_t)(m >> 3) * (3*DIMN);
    float4 sh = *(const float4*)(mrow + tid*4);
    float4 sc = *(const float4*)(mrow + DIMN + tid*4);
    float4 wv = ((const float4*)w)[tid];
    float4 o;
    o.x = v.x*rms*wv.x*(1.f+sc.x) + sh.x;
    o.y = v.y*rms*wv.y*(1.f+sc.y) + sh.y;
    o.z = v.z*rms*wv.z*(1.f+sc.z) + sh.z;
    o.w = v.w*rms*wv.w*(1.f+sc.w) + sh.w;
    ((uint2*)(oh + (size_t)m*DIMN))[tid] = make_uint2(pack_hi(o.x,o.y), pack_hi(o.z,o.w));
    float lx=o.x-hi_part(o.x), ly=o.y-hi_part(o.y);
    float lz=o.z-hi_part(o.z), lw=o.w-hi_part(o.w);
    ((uint2*)(ol + (size_t)m*DIMN))[tid] = make_uint2(pack_hi(lx,ly), pack_hi(lz,lw));
}

/* ---------------- mma block-causal flash attention ------------------------ */
/* CTA: 128 q-rows, 1 head, 1 batch. 8 warps x 16 rows.                      */
/* Double-buffered K/V: Qh[0) Ql[16K); stage s at 32K+s*32K: Kh,Kl,Vh,Vl.    */
#define ATT_SMEM 98304

#define KVISSUE(kt_, st_) do {                                                 \
    size_t rowb = (size_t)(b*SEQL + (kt_)*64)*128 + (h>>2)*32;                 \
    uint32_t sbase = sb + 32768 + (uint32_t)(st_)*32768;                       \
    _Pragma("unroll")                                                          \
    for (int i = 0; i < 2; i++) {                                              \
        int id = tid + i*256;                                                  \
        int r = id >> 3, ch = (id & 7)*4;                                      \
        uint32_t d = (uint32_t)sww32(r, ch)*4;                                 \
        size_t src = rowb + (size_t)r*128 + ch;                                \
        CPA16(sbase + d,         g_kh + src);                                  \
        CPA16(sbase + 8192 + d,  g_kl + src);                                  \
        CPA16(sbase + 16384 + d, g_vh + src);                                  \
        CPA16(sbase + 24576 + d, g_vl + src);                                  \
    }                                                                          \
} while (0)

__global__ __launch_bounds__(256, 2) void attn_kernel(
    bf16* __restrict__ outh, bf16* __restrict__ outl) {
    extern __shared__ uint32_t sm[];
    int qt2 = 7 - blockIdx.x;          /* heavy CTAs launch first */
    int h = blockIdx.y, b = blockIdx.z;
    int tid = threadIdx.x, lane = tid & 31, wid = tid >> 5;
    int g4 = lane >> 2, t4 = lane & 3;
    int lr = lane & 7, sel = lane >> 3;
    int aro = (sel & 1)*8 + lr, awo = (sel >> 1)*4;
    int bro = (sel >> 1)*8 + lr, bwo = (sel & 1)*4;
    int vro = (sel & 1)*8 + lr, vwo = (sel >> 1)*4;
    uint32_t sb = smem_u32(sm);

    /* group 0: Q (hi+lo) + KV stage 0 */
    {
        const uint32_t* qs  = g_qh + (size_t)(b*SEQL + qt2*128)*512 + h*32;
        const uint32_t* qsl = g_ql + (size_t)(b*SEQL + qt2*128)*512 + h*32;
        #pragma unroll
        for (int i = 0; i < 4; i++) {
            int id = tid + i*256;
            int r = id >> 3, ch = (id & 7)*4;
            uint32_t d = (uint32_t)sww32(r, ch)*4;
            CPA16(sb + d,         qs  + (size_t)r*512 + ch);
            CPA16(sb + 16384 + d, qsl + (size_t)r*512 + ch);
        }
    }
    KVISSUE(0, 0);
    CPCOMMIT();

    int kmax = 2*qt2 + (wid >> 2);
    int rb01 = (wid & 3)*2, rb23 = rb01 + 1;
    int base_r = wid*16;
    float s[8][4], o[8][4];
    float m0 = -1e30f, m1 = -1e30f, l0 = 0.f, l1 = 0.f;
    #pragma unroll
    for (int nt=0;nt<8;nt++)
        #pragma unroll
        for (int e=0;e<4;e++) o[nt][e]=0.f;

    int ktend = 2*qt2 + 1;
    for (int kt = 0; kt <= ktend; kt++) {
        if (kt < ktend) {
            KVISSUE(kt+1, (kt+1)&1);
            CPCOMMIT();
            asm volatile("cp.async.wait_group 1;" ::: "memory");
        } else {
            asm volatile("cp.async.wait_group 0;" ::: "memory");
        }
        __syncthreads();
        if (kt <= kmax) {
            uint32_t kvb = sb + 32768 + (uint32_t)(kt&1)*32768;

            /* S = Q @ K^T (split bf16, ldmatrix, per-pair consume) */
            #pragma unroll
            for (int nt=0;nt<8;nt++)
                #pragma unroll
                for (int e=0;e<4;e++) s[nt][e]=0.f;
            #pragma unroll
            for (int ks = 0; ks < 4; ks++) {
                int w0 = ks*8;
                uint32_t ah[4], al[4];
                {
                    int r = base_r + aro;
                    uint32_t ad = sb + (uint32_t)sww32(r, w0+awo)*4;
                    LDSM4(ah[0],ah[1],ah[2],ah[3], ad);
                    LDSM4(al[0],al[1],al[2],al[3], ad + 16384);
                }
                #pragma unroll
                for (int ntp = 0; ntp < 8; ntp += 2) {
                    uint32_t bh[4], bl[4];
                    int r = ntp*8 + bro;
                    uint32_t ad = kvb + (uint32_t)sww32(r, w0+bwo)*4;
                    LDSM4(bh[0],bh[1],bh[2],bh[3], ad);
                    LDSM4(bl[0],bl[1],bl[2],bl[3], ad + 8192);
                    #pragma unroll
                    for (int j = 0; j < 2; j++) {
                        mma_bf16(s[ntp+j], ah, bh + 2*j);
                        mma_bf16(s[ntp+j], ah, bl + 2*j);
                        mma_bf16(s[ntp+j], al, bh + 2*j);
                    }
                }
            }
            #pragma unroll
            for (int nt=0;nt<8;nt++)
                #pragma unroll
                for (int e=0;e<4;e++) s[nt][e] *= 0.125f;
            if (kt == kmax) {
                #pragma unroll
                for (int nt=0;nt<8;nt++) {
                    if (nt > rb01) { s[nt][0] = -1e30f; s[nt][1] = -1e30f; }
                    if (nt > rb23) { s[nt][2] = -1e30f; s[nt][3] = -1e30f; }
                }
            }
            /* online softmax */
            float mx0 = -1e30f, mx1 = -1e30f;
            #pragma unroll
            for (int nt=0;nt<8;nt++) {
                mx0 = fmaxf(mx0, fmaxf(s[nt][0], s[nt][1]));
                mx1 = fmaxf(mx1, fmaxf(s[nt][2], s[nt][3]));
            }
            mx0 = fmaxf(mx0, __shfl_xor_sync(0xffffffffu, mx0, 1));
            mx0 = fmaxf(mx0, __shfl_xor_sync(0xffffffffu, mx0, 2));
            mx1 = fmaxf(mx1, __shfl_xor_sync(0xffffffffu, mx1, 1));
            mx1 = fmaxf(mx1, __shfl_xor_sync(0xffffffffu, mx1, 2));
            float nm0 = fmaxf(m0, mx0), nm1 = fmaxf(m1, mx1);
            float al0 = fexp(m0 - nm0), al1 = fexp(m1 - nm1);
            m0 = nm0; m1 = nm1;
            float sum0 = 0.f, sum1 = 0.f;
            #pragma unroll
            for (int nt=0;nt<8;nt++) {
                s[nt][0] = fexp(s[nt][0] - m0);
                s[nt][1] = fexp(s[nt][1] - m0);
                s[nt][2] = fexp(s[nt][2] - m1);
                s[nt][3] = fexp(s[nt][3] - m1);
                sum0 += s[nt][0] + s[nt][1];
                sum1 += s[nt][2] + s[nt][3];
            }
            sum0 += __shfl_xor_sync(0xffffffffu, sum0, 1);
            sum0 += __shfl_xor_sync(0xffffffffu, sum0, 2);
            sum1 += __shfl_xor_sync(0xffffffffu, sum1, 1);
            sum1 += __shfl_xor_sync(0xffffffffu, sum1, 2);
            l0 = l0*al0 + sum0;
            l1 = l1*al1 + sum1;
            #pragma unroll
            for (int nt=0;nt<8;nt++) {
                o[nt][0] *= al0; o[nt][1] *= al0;
                o[nt][2] *= al1; o[nt][3] *= al1;
            }
            /* O += P @ V (V^T via ldmatrix.trans, per-pair consume) */
            #pragma unroll
            for (int ks = 0; ks < 4; ks++) {
                uint32_t ph[4], pl[4];
                ph[0] = pack_hi(s[2*ks][0],   s[2*ks][1]);
                ph[1] = pack_hi(s[2*ks][2],   s[2*ks][3]);
                ph[2] = pack_hi(s[2*ks+1][0], s[2*ks+1][1]);
                ph[3] = pack_hi(s[2*ks+1][2], s[2*ks+1][3]);
                pl[0] = pack_hi(s[2*ks][0]-hi_part(s[2*ks][0]),
                                s[2*ks][1]-hi_part(s[2*ks][1]));
                pl[1] = pack_hi(s[2*ks][2]-hi_part(s[2*ks][2]),
                                s[2*ks][3]-hi_part(s[2*ks][3]));
                pl[2] = pack_hi(s[2*ks+1][0]-hi_part(s[2*ks+1][0]),
                                s[2*ks+1][1]-hi_part(s[2*ks+1][1]));
                pl[3] = pack_hi(s[2*ks+1][2]-hi_part(s[2*ks+1][2]),
                                s[2*ks+1][3]-hi_part(s[2*ks+1][3]));
                #pragma unroll
                for (int ntp = 0; ntp < 8; ntp += 2) {
                    uint32_t bh[4], bl[4];
                    int rt = ks*16 + vro;
                    uint32_t ad = kvb + 16384 +
                        (uint32_t)sww32(rt, ntp*4 + vwo)*4;
                    LDSM4T(bh[0],bh[1],bh[2],bh[3], ad);
                    LDSM4T(bl[0],bl[1],bl[2],bl[3], ad + 8192);
                    #pragma unroll
                    for (int j = 0; j < 2; j++) {
                        mma_bf16(o[ntp+j], ph, bh + 2*j);
                        mma_bf16(o[ntp+j], ph, bl + 2*j);
                        mma_bf16(o[ntp+j], pl, bh + 2*j);
                    }
                }
            }
        }
        __syncthreads();   /* protect stage buffer before next-iter prefetch */
    }

    /* normalize and write bf16 hi/lo */
    float i0 = 1.f / l0, i1 = 1.f / l1;
    int tok0 = b*SEQL + qt2*128 + base_r + g4;
    #pragma unroll
    for (int nt = 0; nt < 8; nt++) {
        int col = h*64 + nt*8 + 2*t4;
        float x0 = o[nt][0]*i0, x1 = o[nt][1]*i0;
        float x2 = o[nt][2]*i1, x3 = o[nt][3]*i1;
        ((uint32_t*)outh)[((size_t)tok0*DIMN + col) >> 1] = pack_hi(x0, x1);
        ((uint32_t*)outl)[((size_t)tok0*DIMN + col) >> 1] =
            pack_hi(x0-hi_part(x0), x1-hi_part(x1));
        ((uint32_t*)outh)[((size_t)(tok0+8)*DIMN + col) >> 1] = pack_hi(x2, x3);
        ((uint32_t*)outl)[((size_t)(tok0+8)*DIMN + col) >> 1] =
            pack_hi(x2-hi_part(x2), x3-hi_part(x3));
    }
}

/* ---------------- host launcher ------------------------------------------ */
extern "C" void kernel_launch(void* const* d_in, const int* in_sizes, int n_in,
                              void* d_out, int out_size) {
    const float *x,*vec,*wq,*wk,*wv,*wo,*w1,*w2,*w3,*maw,*mab,*mfw,*mfb,*n1,*n2,*fc,*fs;
    if (in_sizes[2] == 32768) {                   /* reference-argument order */
        x  =(const float*)d_in[0];  vec=(const float*)d_in[1];
        fc =(const float*)d_in[2];  fs =(const float*)d_in[3];
        wq =(const float*)d_in[4];  wk =(const float*)d_in[5];
        wv =(const float*)d_in[6];  wo =(const float*)d_in[7];
        w1 =(const float*)d_in[8];  w2 =(const float*)d_in[9];
        w3 =(const float*)d_in[10];
        maw=(const float*)d_in[11]; mab=(const float*)d_in[12];
        mfw=(const float*)d_in[13]; mfb=(const float*)d_in[14];
        n1 =(const float*)d_in[15]; n2 =(const float*)d_in[16];
    } else {                                      /* setup_inputs dict order */
        x  =(const float*)d_in[0];  vec=(const float*)d_in[1];
        wq =(const float*)d_in[2];  wk =(const float*)d_in[3];
        wv =(const float*)d_in[4];  wo =(const float*)d_in[5];
        w1 =(const float*)d_in[6];  w2 =(const float*)d_in[7];
        w3 =(const float*)d_in[8];
        maw=(const float*)d_in[9];  mab=(const float*)d_in[10];
        mfw=(const float*)d_in[11]; mfb=(const float*)d_in[12];
        n1 =(const float*)d_in[13]; n2 =(const float*)d_in[14];
        fc =(const float*)d_in[15]; fs =(const float*)d_in[16];
    }
    float* out = (float*)d_out;

    float *p_ma,*p_mf,*p_h;
    bf16 *p_svh,*p_svl,*p_xnh,*p_xnl,*p_hnh,*p_hnl,*p_ath,*p_atl,*p_g1h,*p_g1l,*p_wh,*p_wl;
    cudaGetSymbolAddress((void**)&p_ma,  g_mod_a);
    cudaGetSymbolAddress((void**)&p_mf,  g_mod_f);
    cudaGetSymbolAddress((void**)&p_h,   g_h);
    cudaGetSymbolAddress((void**)&p_svh, g_svh);
    cudaGetSymbolAddress((void**)&p_svl, g_svl);
    cudaGetSymbolAddress((void**)&p_xnh, g_xnh);
    cudaGetSymbolAddress((void**)&p_xnl, g_xnl);
    cudaGetSymbolAddress((void**)&p_hnh, g_hnh);
    cudaGetSymbolAddress((void**)&p_hnl, g_hnl);
    cudaGetSymbolAddress((void**)&p_ath, g_ath);
    cudaGetSymbolAddress((void**)&p_atl, g_atl);
    cudaGetSymbolAddress((void**)&p_g1h, g_g1h);
    cudaGetSymbolAddress((void**)&p_g1l, g_g1l);
    cudaGetSymbolAddress((void**)&p_wh,  g_wh);
    cudaGetSymbolAddress((void**)&p_wl,  g_wl);

    cudaFuncSetAttribute(attn_kernel,
                         cudaFuncAttributeMaxDynamicSharedMemorySize, ATT_SMEM);
    cudaFuncSetAttribute(gemm_bf<1,2>,
                         cudaFuncAttributeMaxDynamicSharedMemorySize, GSMEM);
    cudaFuncSetAttribute(gemm_bf<3,1>,
                         cudaFuncAttributeMaxDynamicSharedMemorySize, GSMEM);
    cudaFuncSetAttribute(gemm_bf<4,3>,
                         cudaFuncAttributeMaxDynamicSharedMemorySize, GSMEM);
    cudaFuncSetAttribute(gemm_bf<2,0>,
                         cudaFuncAttributeMaxDynamicSharedMemorySize, GSMEM);

    /* 0. all weight converts + silu(vec) in one launch */
    conv_all<<<12288, 256>>>(wq, wk, wv, wo, w1, w3, w2, maw, mfw,
                             p_wh, p_wl, vec, p_svh, p_svl);

    /* 1. both modulation GEMMs in one launch */
    gemm_bf<1,2><<<dim3(48,4), 256, GSMEM>>>(
        p_svh,p_svl, p_wh+OMA,p_wl+OMA, p_wh+OMF,p_wl+OMF, nullptr,nullptr,
        p_ma,p_mf,3*DIMN, DIMN, 24, mab,mfb, nullptr,0, nullptr,0);

    /* 2. xn -> hi/lo */
    rmsnorm_mod_kernel<<<NTOK, 256>>>(x, n1, p_ma, p_xnh, p_xnl);

    /* 3. QKV + fused RoPE -> q/k/v hi/lo buffers */
    gemm_bf<3,1><<<dim3(12,32), 256, GSMEM>>>(
        p_xnh,p_xnl, p_wh+OWQ,p_wl+OWQ, p_wh+OWK,p_wl+OWK, p_wh+OWV,p_wl+OWV,
        nullptr,nullptr,0, DIMN, 0, fc,fs, nullptr,0, nullptr,0);

    /* 4. mma block-causal attention (double-buffered, heavy-first) */
    attn_kernel<<<dim3(8,16,BATCHN), 256, ATT_SMEM>>>(p_ath, p_atl);

    /* 5. h = x + gate_a * (attn @ wo^T) */
    gemm_bf<2,0><<<dim3(8,32), 256, GSMEM>>>(
        p_ath,p_atl, p_wh+OWO,p_wl+OWO, nullptr,nullptr, nullptr,nullptr,
        p_h,nullptr,DIMN, DIMN, 0, nullptr,nullptr, x,DIMN, p_ma, 2*DIMN);

    /* 6. hn -> hi/lo */
    rmsnorm_mod_kernel<<<NTOK, 256>>>(p_h, n2, p_mf, p_hnh, p_hnl);

    /* 7. FFN up w1+w3 + fused swiglu -> bf16 hi/lo (one launch) */
    gemm_bf<4,3><<<dim3(16,32), 256, GSMEM>>>(
        p_hnh,p_hnl, p_wh+OW1,p_wl+OW1, p_wh+OW3,p_wl+OW3, nullptr,nullptr,
        (float*)p_g1h,(float*)p_g1l,0, DIMN, 0, nullptr,nullptr,
        nullptr,0, nullptr,0);

    /* 8. out = h + gate_f * (swiglu @ w2^T) */
    gemm_bf<2,0><<<dim3(8,32), 256, GSMEM>>>(
        p_g1h,p_g1l, p_wh+OW2,p_wl+OW2, nullptr,nullptr, nullptr,nullptr,
        out,nullptr,DIMN, DIMN, 0, nullptr,nullptr, p_h,DIMN, p_mf, 2*DIMN);
}

// round 17
// speedup vs baseline: 1.5330x; 1.0197x over previous
#include <cuda_runtime.h>
#include <cuda_bf16.h>
#include <math.h>
#include <stdint.h>

#define DIMN   1024
#define SEQL   1024
#define BATCHN 4
#define NTOK   (BATCHN*SEQL)     /* 4096 */
#define NBLK   (BATCHN*128)      /* 512 tokens of vec */
#define EPSV   1e-6f

typedef __nv_bfloat16 bf16;

/* ---------------- scratch (device globals: no allocation allowed) -------- */
__device__ float g_mod_a[NBLK*3*DIMN];
__device__ float g_mod_f[NBLK*3*DIMN];
__device__ float g_h[NTOK*DIMN];
/* bf16 hi/lo activation buffers */
__device__ bf16 g_svh[NBLK*DIMN],  g_svl[NBLK*DIMN];
__device__ bf16 g_xnh[NTOK*DIMN],  g_xnl[NTOK*DIMN];
__device__ bf16 g_hnh[NTOK*DIMN],  g_hnl[NTOK*DIMN];
__device__ bf16 g_ath[NTOK*DIMN],  g_atl[NTOK*DIMN];
__device__ bf16 g_g1h[NTOK*DIMN],  g_g1l[NTOK*DIMN];
/* rope'd Q/K and V as packed bf16x2 words, hi and lo */
__device__ uint32_t g_qh[NTOK*512], g_ql[NTOK*512];
__device__ uint32_t g_kh[NTOK*128], g_kl[NTOK*128];
__device__ uint32_t g_vh[NTOK*128], g_vl[NTOK*128];
/* weight hi/lo pool */
#define OWQ  0
#define OWK  1048576
#define OWV  1310720
#define OWO  1572864
#define OW1  2621440
#define OW3  3670016
#define OW2  4718592
#define OMA  5767168
#define OMF  8912896
#define WPOOL 12058624
__device__ bf16 g_wh[WPOOL], g_wl[WPOOL];

/* ---------------- helpers ------------------------------------------------ */
__device__ __forceinline__ uint32_t pack_hi(float x, float y) {
    return __byte_perm(__float_as_uint(x), __float_as_uint(y), 0x7632);
}
__device__ __forceinline__ float hi_part(float x) {
    return __uint_as_float(__float_as_uint(x) & 0xFFFF0000u);
}
__device__ __forceinline__ uint32_t smem_u32(const void* p) {
    uint32_t a;
    asm("{ .reg .u64 t; cvta.to.shared.u64 t, %1; cvt.u32.u64 %0, t; }"
        : "=r"(a) : "l"(p));
    return a;
}
__device__ __forceinline__ int sww16(int r, int w) {
    return r*16 + (w ^ (((r >> 1) & 3) << 2));
}
__device__ __forceinline__ int sww32(int r, int w) {
    return r*32 + (w ^ ((r & 7) << 2));
}
__device__ __forceinline__ void mma_bf16(float* c, const uint32_t* a,
                                         const uint32_t* b) {
    asm volatile(
        "mma.sync.aligned.m16n8k16.row.col.f32.bf16.bf16.f32 "
        "{%0,%1,%2,%3}, {%4,%5,%6,%7}, {%8,%9}, {%0,%1,%2,%3};"
        : "+f"(c[0]), "+f"(c[1]), "+f"(c[2]), "+f"(c[3])
        : "r"(a[0]), "r"(a[1]), "r"(a[2]), "r"(a[3]), "r"(b[0]), "r"(b[1]));
}
#define LDSM4(r0,r1,r2,r3, a) \
    asm volatile("ldmatrix.sync.aligned.m8n8.x4.shared.b16 {%0,%1,%2,%3}, [%4];" \
        : "=r"(r0),"=r"(r1),"=r"(r2),"=r"(r3) : "r"(a))
#define LDSM4T(r0,r1,r2,r3, a) \
    asm volatile("ldmatrix.sync.aligned.m8n8.x4.trans.shared.b16 {%0,%1,%2,%3}, [%4];" \
        : "=r"(r0),"=r"(r1),"=r"(r2),"=r"(r3) : "r"(a))
#define CPA16(dst, src) \
    asm volatile("cp.async.cg.shared.global [%0], [%1], 16;" \
        :: "r"(dst), "l"(src) : "memory")
#define CPCOMMIT() asm volatile("cp.async.commit_group;" ::: "memory")
/* fast exp on FMA pipe */
__device__ __forceinline__ float fexp(float x) {
    float t = fmaxf(x * 1.44269504f, -126.f);
    float fi = floorf(t);
    float f = t - fi;
    float p = fmaf(f, 0.00133336f, 0.00961812f);
    p = fmaf(f, p, 0.05550411f);
    p = fmaf(f, p, 0.24022651f);
    p = fmaf(f, p, 0.69314718f);
    p = fmaf(f, p, 1.0f);
    return __int_as_float(((int)fi + 127) << 23) * p;
}

/* ------------- split-bf16 GEMM via cp.async + ldmatrix -------------------- */
/* BN=128: 2 CTA/SM, 98304B smem.  BN=64: 3 CTA/SM, 73728B smem.             */
#define GS128 98304
#define GS64  73728

#define GISSUE(s_) do {                                                        \
    int kof = (s_)*32;                                                         \
    _Pragma("unroll")                                                          \
    for (int i = 0; i < NITER; i++) {                                          \
        int id = tid + i*256;                                                  \
        int part, loc;                                                         \
        if (id < 1024) { part = id >> 9; loc = id & 511; }                     \
        else { int rem = id - 1024;                                            \
               part = 2 + (rem >= BN*4 ? 1 : 0);                               \
               loc = (rem >= BN*4) ? rem - BN*4 : rem; }                       \
        int row = loc >> 2, chv = loc & 3;                                     \
        const bf16* src;                                                       \
        if (MODE == 3 && part >= 2) {                                          \
            int nlog = (row >> 4)*8 + (row & 7);                               \
            const bf16* wsel = (part==2) ? ((row & 8) ? srcB3h : srcBh)        \
                                         : ((row & 8) ? srcB3l : srcBl);       \
            src = wsel + (size_t)nlog*K + kof + chv*8;                         \
        } else {                                                               \
            const bf16* sp = (part==0) ? srcAh : (part==1) ? srcAl             \
                           : (part==2) ? srcBh : srcBl;                        \
            src = sp + (size_t)row*K + kof + chv*8;                            \
        }                                                                      \
        uint32_t woff = (part < 2) ? (uint32_t)part*2048u                      \
                        : 4096u + (uint32_t)(part-2)*(uint32_t)(BN*16);        \
        uint32_t dst = sb + (uint32_t)((((s_)%3)*STGW + woff                   \
                       + sww16(row, chv*4)) * 4);                              \
        CPA16(dst, src);                                                       \
    }                                                                          \
} while (0)

/* MODE 0: single B/C. MODE 1: qkv (3 Bs). MODE 2: dual B/C split by bx.
   MODE 3: FFN w1/w3 interleaved (BN=128 only), swiglu epilogue (EPI 4).     */
/* EPI 0: C=acc; 1: +bias; 2: resid+mod*acc; 3: rope->q/k/v; 4: swiglu.      */
template<int EPI, int MODE, int BN>
__global__ __launch_bounds__(256, (BN==64) ? 3 : 2) void gemm_bf(
    const bf16* __restrict__ Ah, const bf16* __restrict__ Al,
    const bf16* __restrict__ Bh0, const bf16* __restrict__ Bl0,
    const bf16* __restrict__ Bh1, const bf16* __restrict__ Bl1,
    const bf16* __restrict__ Bh2, const bf16* __restrict__ Bl2,
    float* __restrict__ C0, float* __restrict__ C1, int ldc,
    int K, int split,
    const float* __restrict__ bias0, const float* __restrict__ bias1,
    const float* __restrict__ resid, int ldr,
    const float* __restrict__ mod, int goff) {
    constexpr int NT    = BN/16;            /* n-frags per warp */
    constexpr int STGW  = 4096 + BN*32;     /* words per stage  */
    constexpr int NITER = (1024 + BN*8)/256;
    extern __shared__ uint32_t swm[];
    int tid = threadIdx.x, lane = tid & 31, wid = tid >> 5;
    int wm = wid >> 1, wn = wid & 1;
    int g4 = lane >> 2, t4 = lane & 3;
    int lr = lane & 7, sel = lane >> 3;
    int aro = (sel & 1)*8 + lr, awo = (sel >> 1)*4;
    int bro = (sel >> 1)*8 + lr, bwo = (sel & 1)*4;
    int bx = blockIdx.x, m0 = blockIdx.y*128;
    int n0glob = bx*BN;

    const bf16 *Bh, *Bl, *B3h = nullptr, *B3l = nullptr;
    float* Cg = nullptr; const float* bias = nullptr;
    int n0loc, row0;
    if (MODE == 0) {
        Bh = Bh0; Bl = Bl0; row0 = n0glob; Cg = C0 + n0glob;
        bias = bias0; n0loc = n0glob;
    } else if (MODE == 1) {
        if (n0glob < 1024)      { Bh = Bh0; Bl = Bl0; row0 = n0glob; }
        else if (n0glob < 1280) { Bh = Bh1; Bl = Bl1; row0 = n0glob-1024; }
        else                    { Bh = Bh2; Bl = Bl2; row0 = n0glob-1280; }
        n0loc = n0glob;
    } else if (MODE == 2) {
        int sel2 = bx >= split; int nb = bx - (sel2 ? split : 0);
        n0loc = nb*BN; row0 = n0loc;
        Bh = sel2 ? Bh1 : Bh0;  Bl = sel2 ? Bl1 : Bl0;
        Cg = (sel2 ? C1 : C0) + n0loc;
        bias = sel2 ? bias1 : bias0;
    } else {   /* MODE 3: w1/w3 interleaved, 64 output cols per CTA */
        row0 = bx*64; n0loc = bx*64;
        Bh = Bh0; Bl = Bl0; B3h = Bh1; B3l = Bl1;
    }
    const bf16* srcAh = Ah + (size_t)m0*K;
    const bf16* srcAl = Al + (size_t)m0*K;
    const bf16* srcBh = Bh + (size_t)row0*K;
    const bf16* srcBl = Bl + (size_t)row0*K;
    const bf16* srcB3h = (MODE == 3) ? B3h + (size_t)row0*K : srcBh;
    const bf16* srcB3l = (MODE == 3) ? B3l + (size_t)row0*K : srcBl;
    uint32_t sb = smem_u32(swm);

    int nk = K >> 5;
    GISSUE(0);
    CPCOMMIT();
    GISSUE(1);
    CPCOMMIT();

    float acc[2][NT][4];
    #pragma unroll
    for (int mt=0;mt<2;mt++)
        #pragma unroll
        for (int nt=0;nt<NT;nt++)
            #pragma unroll
            for (int e=0;e<4;e++) acc[mt][nt][e]=0.f;

    for (int s = 0; s < nk; s++) {
        asm volatile("cp.async.wait_group 1;" ::: "memory");
        __syncthreads();
        uint32_t stoff = (uint32_t)((s%3)*STGW*4);
        #pragma unroll
        for (int half = 0; half < 2; half++) {
            int w0 = half*8;
            uint32_t ah[2][4], al[2][4];
            #pragma unroll
            for (int mt = 0; mt < 2; mt++) {
                int r = wm*32 + mt*16 + aro;
                uint32_t ad = sb + stoff + (uint32_t)sww16(r, w0+awo)*4;
                LDSM4(ah[mt][0],ah[mt][1],ah[mt][2],ah[mt][3], ad);
                LDSM4(al[mt][0],al[mt][1],al[mt][2],al[mt][3], ad + 8192);
            }
            #pragma unroll
            for (int ntp = 0; ntp < NT; ntp += 2) {
                uint32_t bh[4], bl[4];
                int r = wn*(BN/2) + ntp*8 + bro;
                uint32_t ad = sb + stoff + 16384u
                            + (uint32_t)sww16(r, w0+bwo)*4;
                LDSM4(bh[0],bh[1],bh[2],bh[3], ad);
                LDSM4(bl[0],bl[1],bl[2],bl[3], ad + (uint32_t)(BN*64));
                #pragma unroll
                for (int j = 0; j < 2; j++) {
                    int nt = ntp + j;
                    #pragma unroll
                    for (int mt = 0; mt < 2; mt++) {
                        mma_bf16(acc[mt][nt], ah[mt], bh + 2*j);
                        mma_bf16(acc[mt][nt], ah[mt], bl + 2*j);
                        mma_bf16(acc[mt][nt], al[mt], bh + 2*j);
                    }
                }
            }
        }
        if (s + 2 < nk) { GISSUE(s+2); }
        CPCOMMIT();
    }

    if (EPI == 4) {
        /* swiglu epilogue: pair (ntp even = g1, ntp+1 = g3), write bf16 */
        uint32_t* oh = (uint32_t*)C0;
        uint32_t* ol = (uint32_t*)C1;
        #pragma unroll
        for (int mt = 0; mt < 2; mt++) {
            int rb0 = m0 + wm*32 + mt*16 + g4;
            #pragma unroll
            for (int h = 0; h < 2; h++) {
                int m = rb0 + h*8;
                #pragma unroll
                for (int ntp = 0; ntp < NT; ntp += 2) {
                    int col = n0loc + wn*32 + (ntp>>1)*8 + 2*t4;
                    float gA = acc[mt][ntp][2*h],   gB = acc[mt][ntp][2*h+1];
                    float uA = acc[mt][ntp+1][2*h], uB = acc[mt][ntp+1][2*h+1];
                    float x0 = gA / (1.f + fexp(-gA)) * uA;
                    float x1 = gB / (1.f + fexp(-gB)) * uB;
                    size_t w = ((size_t)m*DIMN + col) >> 1;
                    oh[w] = pack_hi(x0, x1);
                    ol[w] = pack_hi(x0-hi_part(x0), x1-hi_part(x1));
                }
            }
        }
        return;
    }

    #pragma unroll
    for (int mt = 0; mt < 2; mt++) {
        int rb0 = m0 + wm*32 + mt*16 + g4;
        #pragma unroll
        for (int h = 0; h < 2; h++) {
            int m = rb0 + h*8;
            #pragma unroll
            for (int nt = 0; nt < NT; nt++) {
                int nl = wn*(BN/2) + nt*8 + 2*t4;
                float2 a2 = make_float2(acc[mt][nt][2*h], acc[mt][nt][2*h+1]);
                if (EPI == 3) {
                    int ng = n0loc + nl;
                    if (ng < 1280) {
                        int t = m & (SEQL-1); int dp = (ng & 63) >> 1;
                        float c = bias0[t*32+dp], sn = bias1[t*32+dp];
                        float r0 = a2.x*c - a2.y*sn, r1 = a2.x*sn + a2.y*c;
                        a2.x = r0; a2.y = r1;
                    }
                    uint32_t hw = pack_hi(a2.x, a2.y);
                    uint32_t lw = pack_hi(a2.x-hi_part(a2.x), a2.y-hi_part(a2.y));
                    if (ng < 1024) {
                        g_qh[(size_t)m*512 + (ng>>1)] = hw;
                        g_ql[(size_t)m*512 + (ng>>1)] = lw;
                    } else if (ng < 1280) {
                        int c = (ng-1024)>>1;
                        g_kh[(size_t)m*128 + c] = hw;
                        g_kl[(size_t)m*128 + c] = lw;
                    } else {
                        int c = (ng-1280)>>1;
                        g_vh[(size_t)m*128 + c] = hw;
                        g_vl[(size_t)m*128 + c] = lw;
                    }
                } else {
                    float2 o;
                    if (EPI == 0) {
                        o = a2;
                    } else if (EPI == 1) {
                        const float2 bv = *(const float2*)(bias + n0loc + nl);
                        o.x = a2.x + bv.x; o.y = a2.y + bv.y;
                    } else {
                        int ng = n0loc + nl;
                        const float2 gv = *(const float2*)(mod + (size_t)(m>>3)*(3*DIMN) + goff + ng);
                        const float2 rv = *(const float2*)(resid + (size_t)m*ldr + ng);
                        o.x = rv.x + gv.x*a2.x;
                        o.y = rv.y + gv.y*a2.y;
                    }
                    *(float2*)(Cg + (size_t)m*ldc + nl) = o;
                }
            }
        }
    }
}

/* -------- weight convert, two phases (+silu in phase 0) ------------------ */
__global__ __launch_bounds__(256) void conv_phase(
    int phase,
    const float* __restrict__ wq, const float* __restrict__ wk,
    const float* __restrict__ wv, const float* __restrict__ wo,
    const float* __restrict__ w1, const float* __restrict__ w3,
    const float* __restrict__ w2, const float* __restrict__ maw,
    const float* __restrict__ mfw,
    bf16* __restrict__ wh, bf16* __restrict__ wl,
    const float* __restrict__ vec,
    bf16* __restrict__ svh, bf16* __restrict__ svl) {
    int bb = blockIdx.x;
    const float* src; int loc, dof;
    if (phase == 0) {
        if (bb >= 7680) {    /* silu(vec) tail: 512 blocks */
            int i = (bb - 7680)*256 + threadIdx.x;
            float4 v = ((const float4*)vec)[i];
            float4 o;
            o.x = v.x / (1.f + __expf(-v.x));
            o.y = v.y / (1.f + __expf(-v.y));
            o.z = v.z / (1.f + __expf(-v.z));
            o.w = v.w / (1.f + __expf(-v.w));
            ((uint2*)svh)[i] = make_uint2(pack_hi(o.x,o.y), pack_hi(o.z,o.w));
            float lx=o.x-hi_part(o.x), ly=o.y-hi_part(o.y);
            float lz=o.z-hi_part(o.z), lw=o.w-hi_part(o.w);
            ((uint2*)svl)[i] = make_uint2(pack_hi(lx,ly), pack_hi(lz,lw));
            return;
        }
        if      (bb < 1024) { src = wq;  loc = bb;       dof = OWQ; }
        else if (bb < 1280) { src = wk;  loc = bb-1024;  dof = OWK; }
        else if (bb < 1536) { src = wv;  loc = bb-1280;  dof = OWV; }
        else if (bb < 4608) { src = maw; loc = bb-1536;  dof = OMA; }
        else                { src = mfw; loc = bb-4608;  dof = OMF; }
    } else {
        if      (bb < 1024) { src = wo;  loc = bb;       dof = OWO; }
        else if (bb < 2048) { src = w1;  loc = bb-1024;  dof = OW1; }
        else if (bb < 3072) { src = w3;  loc = bb-2048;  dof = OW3; }
        else                { src = w2;  loc = bb-3072;  dof = OW2; }
    }
    int i = loc*256 + threadIdx.x;
    float4 v = ((const float4*)src)[i];
    ((uint2*)(wh + dof))[i] = make_uint2(pack_hi(v.x,v.y), pack_hi(v.z,v.w));
    float lx=v.x-hi_part(v.x), ly=v.y-hi_part(v.y);
    float lz=v.z-hi_part(v.z), lw=v.w-hi_part(v.w);
    ((uint2*)(wl + dof))[i] = make_uint2(pack_hi(lx,ly), pack_hi(lz,lw));
}

/* ---------------- rmsnorm + modulate -> bf16 hi/lo ----------------------- */
__global__ __launch_bounds__(256) void rmsnorm_mod_kernel(
    const float* __restrict__ X, const float* __restrict__ w,
    const float* __restrict__ mod, bf16* __restrict__ oh, bf16* __restrict__ ol) {
    int m = blockIdx.x;
    int tid = threadIdx.x;
    float4 v = ((const float4*)(X + (size_t)m*DIMN))[tid];
    float ss = v.x*v.x + v.y*v.y + v.z*v.z + v.w*v.w;
    #pragma unroll
    for (int o = 16; o; o >>= 1) ss += __shfl_xor_sync(0xffffffffu, ss, o);
    __shared__ float red[8];
    if ((tid & 31) == 0) red[tid >> 5] = ss;
    __syncthreads();
    float tot = red[0]+red[1]+red[2]+red[3]+red[4]+red[5]+red[6]+red[7];
    float rms = rsqrtf(tot * (1.f/DIMN) + EPSV);
    const float* mrow = mod + (size_t)(m >> 3) * (3*DIMN);
    float4 sh = *(const float4*)(mrow + tid*4);
    float4 sc = *(const float4*)(mrow + DIMN + tid*4);
    float4 wv = ((const float4*)w)[tid];
    float4 o;
    o.x = v.x*rms*wv.x*(1.f+sc.x) + sh.x;
    o.y = v.y*rms*wv.y*(1.f+sc.y) + sh.y;
    o.z = v.z*rms*wv.z*(1.f+sc.z) + sh.z;
    o.w = v.w*rms*wv.w*(1.f+sc.w) + sh.w;
    ((uint2*)(oh + (size_t)m*DIMN))[tid] = make_uint2(pack_hi(o.x,o.y), pack_hi(o.z,o.w));
    float lx=o.x-hi_part(o.x), ly=o.y-hi_part(o.y);
    float lz=o.z-hi_part(o.z), lw=o.w-hi_part(o.w);
    ((uint2*)(ol + (size_t)m*DIMN))[tid] = make_uint2(pack_hi(lx,ly), pack_hi(lz,lw));
}

/* ---------------- mma block-causal flash attention ------------------------ */
#define ATT_SMEM 98304

#define KVISSUE(kt_, st_) do {                                                 \
    size_t rowb = (size_t)(b*SEQL + (kt_)*64)*128 + (h>>2)*32;                 \
    uint32_t sbase = sb + 32768 + (uint32_t)(st_)*32768;                       \
    _Pragma("unroll")                                                          \
    for (int i = 0; i < 2; i++) {                                              \
        int id = tid + i*256;                                                  \
        int r = id >> 3, ch = (id & 7)*4;                                      \
        uint32_t d = (uint32_t)sww32(r, ch)*4;                                 \
        size_t src = rowb + (size_t)r*128 + ch;                                \
        CPA16(sbase + d,         g_kh + src);                                  \
        CPA16(sbase + 8192 + d,  g_kl + src);                                  \
        CPA16(sbase + 16384 + d, g_vh + src);                                  \
        CPA16(sbase + 24576 + d, g_vl + src);                                  \
    }                                                                          \
} while (0)

__global__ __launch_bounds__(256, 2) void attn_kernel(
    bf16* __restrict__ outh, bf16* __restrict__ outl) {
    extern __shared__ uint32_t sm[];
    int qt2 = 7 - blockIdx.x;          /* heavy CTAs launch first */
    int h = blockIdx.y, b = blockIdx.z;
    int tid = threadIdx.x, lane = tid & 31, wid = tid >> 5;
    int g4 = lane >> 2, t4 = lane & 3;
    int lr = lane & 7, sel = lane >> 3;
    int aro = (sel & 1)*8 + lr, awo = (sel >> 1)*4;
    int bro = (sel >> 1)*8 + lr, bwo = (sel & 1)*4;
    int vro = (sel & 1)*8 + lr, vwo = (sel >> 1)*4;
    uint32_t sb = smem_u32(sm);

    {
        const uint32_t* qs  = g_qh + (size_t)(b*SEQL + qt2*128)*512 + h*32;
        const uint32_t* qsl = g_ql + (size_t)(b*SEQL + qt2*128)*512 + h*32;
        #pragma unroll
        for (int i = 0; i < 4; i++) {
            int id = tid + i*256;
            int r = id >> 3, ch = (id & 7)*4;
            uint32_t d = (uint32_t)sww32(r, ch)*4;
            CPA16(sb + d,         qs  + (size_t)r*512 + ch);
            CPA16(sb + 16384 + d, qsl + (size_t)r*512 + ch);
        }
    }
    KVISSUE(0, 0);
    CPCOMMIT();

    int kmax = 2*qt2 + (wid >> 2);
    int rb01 = (wid & 3)*2, rb23 = rb01 + 1;
    int base_r = wid*16;
    float s[8][4], o[8][4];
    float m0 = -1e30f, m1 = -1e30f, l0 = 0.f, l1 = 0.f;
    #pragma unroll
    for (int nt=0;nt<8;nt++)
        #pragma unroll
        for (int e=0;e<4;e++) o[nt][e]=0.f;

    int ktend = 2*qt2 + 1;
    for (int kt = 0; kt <= ktend; kt++) {
        if (kt < ktend) {
            KVISSUE(kt+1, (kt+1)&1);
            CPCOMMIT();
            asm volatile("cp.async.wait_group 1;" ::: "memory");
        } else {
            asm volatile("cp.async.wait_group 0;" ::: "memory");
        }
        __syncthreads();
        if (kt <= kmax) {
            uint32_t kvb = sb + 32768 + (uint32_t)(kt&1)*32768;

            #pragma unroll
            for (int nt=0;nt<8;nt++)
                #pragma unroll
                for (int e=0;e<4;e++) s[nt][e]=0.f;
            #pragma unroll
            for (int ks = 0; ks < 4; ks++) {
                int w0 = ks*8;
                uint32_t ah[4], al[4];
                {
                    int r = base_r + aro;
                    uint32_t ad = sb + (uint32_t)sww32(r, w0+awo)*4;
                    LDSM4(ah[0],ah[1],ah[2],ah[3], ad);
                    LDSM4(al[0],al[1],al[2],al[3], ad + 16384);
                }
                #pragma unroll
                for (int ntp = 0; ntp < 8; ntp += 2) {
                    uint32_t bh[4], bl[4];
                    int r = ntp*8 + bro;
                    uint32_t ad = kvb + (uint32_t)sww32(r, w0+bwo)*4;
                    LDSM4(bh[0],bh[1],bh[2],bh[3], ad);
                    LDSM4(bl[0],bl[1],bl[2],bl[3], ad + 8192);
                    #pragma unroll
                    for (int j = 0; j < 2; j++) {
                        mma_bf16(s[ntp+j], ah, bh + 2*j);
                        mma_bf16(s[ntp+j], ah, bl + 2*j);
                        mma_bf16(s[ntp+j], al, bh + 2*j);
                    }
                }
            }
            #pragma unroll
            for (int nt=0;nt<8;nt++)
                #pragma unroll
                for (int e=0;e<4;e++) s[nt][e] *= 0.125f;
            if (kt == kmax) {
                #pragma unroll
                for (int nt=0;nt<8;nt++) {
                    if (nt > rb01) { s[nt][0] = -1e30f; s[nt][1] = -1e30f; }
                    if (nt > rb23) { s[nt][2] = -1e30f; s[nt][3] = -1e30f; }
                }
            }
            float mx0 = -1e30f, mx1 = -1e30f;
            #pragma unroll
            for (int nt=0;nt<8;nt++) {
                mx0 = fmaxf(mx0, fmaxf(s[nt][0], s[nt][1]));
                mx1 = fmaxf(mx1, fmaxf(s[nt][2], s[nt][3]));
            }
            mx0 = fmaxf(mx0, __shfl_xor_sync(0xffffffffu, mx0, 1));
            mx0 = fmaxf(mx0, __shfl_xor_sync(0xffffffffu, mx0, 2));
            mx1 = fmaxf(mx1, __shfl_xor_sync(0xffffffffu, mx1, 1));
            mx1 = fmaxf(mx1, __shfl_xor_sync(0xffffffffu, mx1, 2));
            float nm0 = fmaxf(m0, mx0), nm1 = fmaxf(m1, mx1);
            float al0 = fexp(m0 - nm0), al1 = fexp(m1 - nm1);
            m0 = nm0; m1 = nm1;
            float sum0 = 0.f, sum1 = 0.f;
            #pragma unroll
            for (int nt=0;nt<8;nt++) {
                s[nt][0] = fexp(s[nt][0] - m0);
                s[nt][1] = fexp(s[nt][1] - m0);
                s[nt][2] = fexp(s[nt][2] - m1);
                s[nt][3] = fexp(s[nt][3] - m1);
                sum0 += s[nt][0] + s[nt][1];
                sum1 += s[nt][2] + s[nt][3];
            }
            sum0 += __shfl_xor_sync(0xffffffffu, sum0, 1);
            sum0 += __shfl_xor_sync(0xffffffffu, sum0, 2);
            sum1 += __shfl_xor_sync(0xffffffffu, sum1, 1);
            sum1 += __shfl_xor_sync(0xffffffffu, sum1, 2);
            l0 = l0*al0 + sum0;
            l1 = l1*al1 + sum1;
            #pragma unroll
            for (int nt=0;nt<8;nt++) {
                o[nt][0] *= al0; o[nt][1] *= al0;
                o[nt][2] *= al1; o[nt][3] *= al1;
            }
            #pragma unroll
            for (int ks = 0; ks < 4; ks++) {
                uint32_t ph[4], pl[4];
                ph[0] = pack_hi(s[2*ks][0],   s[2*ks][1]);
                ph[1] = pack_hi(s[2*ks][2],   s[2*ks][3]);
                ph[2] = pack_hi(s[2*ks+1][0], s[2*ks+1][1]);
                ph[3] = pack_hi(s[2*ks+1][2], s[2*ks+1][3]);
                pl[0] = pack_hi(s[2*ks][0]-hi_part(s[2*ks][0]),
                                s[2*ks][1]-hi_part(s[2*ks][1]));
                pl[1] = pack_hi(s[2*ks][2]-hi_part(s[2*ks][2]),
                                s[2*ks][3]-hi_part(s[2*ks][3]));
                pl[2] = pack_hi(s[2*ks+1][0]-hi_part(s[2*ks+1][0]),
                                s[2*ks+1][1]-hi_part(s[2*ks+1][1]));
                pl[3] = pack_hi(s[2*ks+1][2]-hi_part(s[2*ks+1][2]),
                                s[2*ks+1][3]-hi_part(s[2*ks+1][3]));
                #pragma unroll
                for (int ntp = 0; ntp < 8; ntp += 2) {
                    uint32_t bh[4], bl[4];
                    int rt = ks*16 + vro;
                    uint32_t ad = kvb + 16384 +
                        (uint32_t)sww32(rt, ntp*4 + vwo)*4;
                    LDSM4T(bh[0],bh[1],bh[2],bh[3], ad);
                    LDSM4T(bl[0],bl[1],bl[2],bl[3], ad + 8192);
                    #pragma unroll
                    for (int j = 0; j < 2; j++) {
                        mma_bf16(o[ntp+j], ph, bh + 2*j);
                        mma_bf16(o[ntp+j], ph, bl + 2*j);
                        mma_bf16(o[ntp+j], pl, bh + 2*j);
                    }
                }
            }
        }
        __syncthreads();
    }

    float i0 = 1.f / l0, i1 = 1.f / l1;
    int tok0 = b*SEQL + qt2*128 + base_r + g4;
    #pragma unroll
    for (int nt = 0; nt < 8; nt++) {
        int col = h*64 + nt*8 + 2*t4;
        float x0 = o[nt][0]*i0, x1 = o[nt][1]*i0;
        float x2 = o[nt][2]*i1, x3 = o[nt][3]*i1;
        ((uint32_t*)outh)[((size_t)tok0*DIMN + col) >> 1] = pack_hi(x0, x1);
        ((uint32_t*)outl)[((size_t)tok0*DIMN + col) >> 1] =
            pack_hi(x0-hi_part(x0), x1-hi_part(x1));
        ((uint32_t*)outh)[((size_t)(tok0+8)*DIMN + col) >> 1] = pack_hi(x2, x3);
        ((uint32_t*)outl)[((size_t)(tok0+8)*DIMN + col) >> 1] =
            pack_hi(x2-hi_part(x2), x3-hi_part(x3));
    }
}

/* ---------------- host launcher ------------------------------------------ */
extern "C" void kernel_launch(void* const* d_in, const int* in_sizes, int n_in,
                              void* d_out, int out_size) {
    const float *x,*vec,*wq,*wk,*wv,*wo,*w1,*w2,*w3,*maw,*mab,*mfw,*mfb,*n1,*n2,*fc,*fs;
    if (in_sizes[2] == 32768) {                   /* reference-argument order */
        x  =(const float*)d_in[0];  vec=(const float*)d_in[1];
        fc =(const float*)d_in[2];  fs =(const float*)d_in[3];
        wq =(const float*)d_in[4];  wk =(const float*)d_in[5];
        wv =(const float*)d_in[6];  wo =(const float*)d_in[7];
        w1 =(const float*)d_in[8];  w2 =(const float*)d_in[9];
        w3 =(const float*)d_in[10];
        maw=(const float*)d_in[11]; mab=(const float*)d_in[12];
        mfw=(const float*)d_in[13]; mfb=(const float*)d_in[14];
        n1 =(const float*)d_in[15]; n2 =(const float*)d_in[16];
    } else {                                      /* setup_inputs dict order */
        x  =(const float*)d_in[0];  vec=(const float*)d_in[1];
        wq =(const float*)d_in[2];  wk =(const float*)d_in[3];
        wv =(const float*)d_in[4];  wo =(const float*)d_in[5];
        w1 =(const float*)d_in[6];  w2 =(const float*)d_in[7];
        w3 =(const float*)d_in[8];
        maw=(const float*)d_in[9];  mab=(const float*)d_in[10];
        mfw=(const float*)d_in[11]; mfb=(const float*)d_in[12];
        n1 =(const float*)d_in[13]; n2 =(const float*)d_in[14];
        fc =(const float*)d_in[15]; fs =(const float*)d_in[16];
    }
    float* out = (float*)d_out;

    float *p_ma,*p_mf,*p_h;
    bf16 *p_svh,*p_svl,*p_xnh,*p_xnl,*p_hnh,*p_hnl,*p_ath,*p_atl,*p_g1h,*p_g1l,*p_wh,*p_wl;
    cudaGetSymbolAddress((void**)&p_ma,  g_mod_a);
    cudaGetSymbolAddress((void**)&p_mf,  g_mod_f);
    cudaGetSymbolAddress((void**)&p_h,   g_h);
    cudaGetSymbolAddress((void**)&p_svh, g_svh);
    cudaGetSymbolAddress((void**)&p_svl, g_svl);
    cudaGetSymbolAddress((void**)&p_xnh, g_xnh);
    cudaGetSymbolAddress((void**)&p_xnl, g_xnl);
    cudaGetSymbolAddress((void**)&p_hnh, g_hnh);
    cudaGetSymbolAddress((void**)&p_hnl, g_hnl);
    cudaGetSymbolAddress((void**)&p_ath, g_ath);
    cudaGetSymbolAddress((void**)&p_atl, g_atl);
    cudaGetSymbolAddress((void**)&p_g1h, g_g1h);
    cudaGetSymbolAddress((void**)&p_g1l, g_g1l);
    cudaGetSymbolAddress((void**)&p_wh,  g_wh);
    cudaGetSymbolAddress((void**)&p_wl,  g_wl);

    cudaFuncSetAttribute(attn_kernel,
                         cudaFuncAttributeMaxDynamicSharedMemorySize, ATT_SMEM);
    cudaFuncSetAttribute(gemm_bf<1,2,64>,
                         cudaFuncAttributeMaxDynamicSharedMemorySize, GS64);
    cudaFuncSetAttribute(gemm_bf<3,1,64>,
                         cudaFuncAttributeMaxDynamicSharedMemorySize, GS64);
    cudaFuncSetAttribute(gemm_bf<4,3,128>,
                         cudaFuncAttributeMaxDynamicSharedMemorySize, GS128);
    cudaFuncSetAttribute(gemm_bf<2,0,128>,
                         cudaFuncAttributeMaxDynamicSharedMemorySize, GS128);

    /* one-time stream/event handles (no device memory involved) */
    static cudaStream_t s2 = nullptr;
    static cudaEvent_t evF = nullptr, evJ = nullptr;
    if (!s2) {
        cudaStreamCreate(&s2);
        cudaEventCreateWithFlags(&evF, cudaEventDisableTiming);
        cudaEventCreateWithFlags(&evJ, cudaEventDisableTiming);
    }

    /* fork: phase-1 weight conversion (wo/w1/w3/w2) on side stream */
    cudaEventRecord(evF, 0);
    cudaStreamWaitEvent(s2, evF, 0);
    conv_phase<<<4096, 256, 0, s2>>>(1, wq, wk, wv, wo, w1, w3, w2, maw, mfw,
                                     p_wh, p_wl, vec, p_svh, p_svl);
    cudaEventRecord(evJ, s2);

    /* 0. phase-0 converts (wq/wk/wv/maw/mfw) + silu(vec) */
    conv_phase<<<8192, 256>>>(0, wq, wk, wv, wo, w1, w3, w2, maw, mfw,
                              p_wh, p_wl, vec, p_svh, p_svl);

    /* 1. both modulation GEMMs in one launch (BN=64, 384 CTAs) */
    gemm_bf<1,2,64><<<dim3(96,4), 256, GS64>>>(
        p_svh,p_svl, p_wh+OMA,p_wl+OMA, p_wh+OMF,p_wl+OMF, nullptr,nullptr,
        p_ma,p_mf,3*DIMN, DIMN, 48, mab,mfb, nullptr,0, nullptr,0);

    /* 2. xn -> hi/lo */
    rmsnorm_mod_kernel<<<NTOK, 256>>>(x, n1, p_ma, p_xnh, p_xnl);

    /* 3. QKV + fused RoPE (BN=64, 768 CTAs) */
    gemm_bf<3,1,64><<<dim3(24,32), 256, GS64>>>(
        p_xnh,p_xnl, p_wh+OWQ,p_wl+OWQ, p_wh+OWK,p_wl+OWK, p_wh+OWV,p_wl+OWV,
        nullptr,nullptr,0, DIMN, 0, fc,fs, nullptr,0, nullptr,0);

    /* 4. mma block-causal attention */
    attn_kernel<<<dim3(8,16,BATCHN), 256, ATT_SMEM>>>(p_ath, p_atl);

    /* join side-stream conversions before first use of wo */
    cudaStreamWaitEvent(0, evJ, 0);

    /* 5. h = x + gate_a * (attn @ wo^T) */
    gemm_bf<2,0,128><<<dim3(8,32), 256, GS128>>>(
        p_ath,p_atl, p_wh+OWO,p_wl+OWO, nullptr,nullptr, nullptr,nullptr,
        p_h,nullptr,DIMN, DIMN, 0, nullptr,nullptr, x,DIMN, p_ma, 2*DIMN);

    /* 6. hn -> hi/lo */
    rmsnorm_mod_kernel<<<NTOK, 256>>>(p_h, n2, p_mf, p_hnh, p_hnl);

    /* 7. FFN up w1+w3 + fused swiglu (BN=128, interleaved) */
    gemm_bf<4,3,128><<<dim3(16,32), 256, GS128>>>(
        p_hnh,p_hnl, p_wh+OW1,p_wl+OW1, p_wh+OW3,p_wl+OW3, nullptr,nullptr,
        (float*)p_g1h,(float*)p_g1l,0, DIMN, 0, nullptr,nullptr,
        nullptr,0, nullptr,0);

    /* 8. out = h + gate_f * (swiglu @ w2^T) */
    gemm_bf<2,0,128><<<dim3(8,32), 256, GS128>>>(
        p_g1h,p_g1l, p_wh+OW2,p_wl+OW2, nullptr,nullptr, nullptr,nullptr,
        out,nullptr,DIMN, DIMN, 0, nullptr,nullptr, p_h,DIMN, p_mf, 2*DIMN);
}